// round 11
// baseline (speedup 1.0000x reference)
#include <cuda_runtime.h>
#include <math.h>

#define B_   4
#define T_   32
#define N_   370
#define E_   11840
#define E2_  (E_ + N_)
#define G_   128
#define H_   64
#define GN   (G_ * N_)
#define NH   (N_ * H_)
#define CHUNK_ 512
#define DCAP 256

typedef unsigned long long u64;
__device__ __forceinline__ u64 pk2(float lo, float hi) {
    u64 r; asm("mov.b64 %0,{%1,%2};" : "=l"(r) : "f"(lo), "f"(hi)); return r;
}
__device__ __forceinline__ void upk2(u64 v, float& lo, float& hi) {
    asm("mov.b64 {%0,%1},%2;" : "=f"(lo), "=f"(hi) : "l"(v));
}
__device__ __forceinline__ u64 fma2(u64 a, u64 b, u64 c) {
    u64 d; asm("fma.rn.f32x2 %0,%1,%2,%3;" : "=l"(d) : "l"(a), "l"(b), "l"(c)); return d;
}

__device__ float d_xin[GN * H_];
__device__ int   d_eic[2 * E_];
__device__ float d_ewc[E_];
__device__ float d_Wg[3 * 4096];
__device__ float d_bg[3 * 64];
__device__ float d_Wa[3 * 4096];
__device__ float d_asw[3 * 64];
__device__ float d_adw[3 * 64];
__device__ float d_ba[3 * 64];
__device__ float d_Wt[3 * 20480];
__device__ float d_bt[3 * 64];
__device__ float d_lngc[3 * 64];
__device__ float d_lnbc[3 * 64];
__device__ float d_W1c[NH * 256];
__device__ float d_b1c[256];
__device__ float d_W2c[256 * 64];
__device__ float d_b2c[64];

__device__ float  d_h[GN * H_];
__device__ int    d_csr_ptr[N_ + 1];
__device__ int    d_csr_eid[E2_];
__device__ int    d_csr_dst[E2_];
__device__ float2 d_csr_sg[E2_];
__device__ int    d_cnt[CHUNK_ * N_];
__device__ float  d_xt0[B_ * N_ * H_ * T_];
__device__ float  d_part[N_ * G_ * 256];

__device__ __forceinline__ float gelu_f(float x) {
    return 0.5f * x * (1.0f + erff(x * 0.70710678118654752f));
}

// ---------------- staging ----------------
__global__ void k_stageA(const int* ei, const float* ew, const float* Wg,
                         const float* bg, const float* Wa, const float* asw,
                         const float* adw, const float* ba, const float* lng,
                         const float* lnb) {
    int i0 = blockIdx.x * 256 + threadIdx.x, st = gridDim.x * 256;
    for (int i = i0; i < 2 * E_; i += st) d_eic[i] = ei[i];
    for (int i = i0; i < E_;    i += st) d_ewc[i] = ew[i];
    for (int i = i0; i < 12288; i += st) { d_Wg[i] = Wg[i]; d_Wa[i] = Wa[i]; }
    for (int i = i0; i < CHUNK_ * N_; i += st) d_cnt[i] = 0;
    for (int i = i0; i < 192;   i += st) {
        d_bg[i] = bg[i]; d_asw[i] = asw[i]; d_adw[i] = adw[i];
        d_ba[i] = ba[i]; d_lngc[i] = lng[i]; d_lnbc[i] = lnb[i];
    }
}
__global__ void k_stageB(const float* Wt, const float* bt, const float* b1,
                         const float* W2, const float* b2) {
    int i0 = blockIdx.x * 256 + threadIdx.x, st = gridDim.x * 256;
    for (int i = i0; i < 61440; i += st) d_Wt[i] = Wt[i];
    for (int i = i0; i < 192;   i += st) d_bt[i] = bt[i];
    for (int i = i0; i < 256;   i += st) d_b1c[i] = b1[i];
    for (int i = i0; i < 16384; i += st) d_W2c[i] = W2[i];
    for (int i = i0; i < 64;    i += st) d_b2c[i] = b2[i];
}

// ---------------- prep: CSR + deg + gnorm, one block ----------------
__global__ void k_prepAll() {
    int t = threadIdx.x;
    const int* dsts = d_eic + E_;
    const int EC = (E_ + CHUNK_ - 1) / CHUNK_;
    int e0 = t * EC, e1 = min(e0 + EC, E_);
    __shared__ int   ptr_s[N_ + 1];
    __shared__ float dis_s[N_];
    for (int e = e0; e < e1; e++) d_cnt[t * N_ + dsts[e]]++;
    __syncthreads();
    if (t < N_) {
        int run = 0;
        for (int c = 0; c < CHUNK_; c++) {
            int idx = c * N_ + t;
            int v = d_cnt[idx]; d_cnt[idx] = run; run += v;
        }
        ptr_s[t] = run + 1;
    }
    __syncthreads();
    if (t == 0) {
        int p = 0;
        for (int n = 0; n < N_; n++) { int v = ptr_s[n]; ptr_s[n] = p; p += v; }
        ptr_s[N_] = p;
    }
    __syncthreads();
    if (t <= N_) d_csr_ptr[t] = ptr_s[t];
    for (int e = e0; e < e1; e++) {
        int d = dsts[e];
        int pos = ptr_s[d] + d_cnt[t * N_ + d]++;
        d_csr_eid[pos] = e; d_csr_dst[pos] = d;
    }
    __syncthreads();
    if (t < N_) {
        int pos = ptr_s[t + 1] - 1;
        d_csr_eid[pos] = E_ + t; d_csr_dst[pos] = t;
    }
    __syncthreads();
    // degree -> dis
    for (int n = t; n < N_; n += CHUNK_) {
        float s = 1.0f;
        for (int p = ptr_s[n]; p < ptr_s[n + 1] - 1; p++) s += d_ewc[d_csr_eid[p]];
        dis_s[n] = rsqrtf(s);
    }
    __syncthreads();
    // packed (src, gnorm)
    for (int pos = t; pos < E2_; pos += CHUNK_) {
        int e = d_csr_eid[pos], d = d_csr_dst[pos];
        float dd = dis_s[d];
        int s; float gn;
        if (e < E_) { s = d_eic[e]; gn = dis_s[s] * d_ewc[e] * dd; }
        else        { s = d;        gn = dd * dd; }
        d_csr_sg[pos] = make_float2(__int_as_float(s), gn);
    }
}

// ------- in-block 370x64 @ 64x64 GEMM (512 threads), scalar FFMA -------
__device__ __forceinline__ void gemm_block(const float* __restrict__ in_s,
                                           const float* __restrict__ WsT,
                                           float* __restrict__ out_s, int tid) {
    int c = tid & 63, rb = tid >> 6;
    const float* wc = WsT + c * 68;
    float w[64];
    #pragma unroll
    for (int k = 0; k < 64; k += 4) *(float4*)&w[k] = *(const float4*)&wc[k];
    for (int r = rb; r < 185; r += 8) {
        int r2 = r + 185;
        float a0 = 0.f, a1 = 0.f, a2 = 0.f, a3 = 0.f;
        #pragma unroll
        for (int k = 0; k < 64; k += 4) {
            float4 h0 = *(const float4*)&in_s[r * 64 + k];
            float4 h1 = *(const float4*)&in_s[r2 * 64 + k];
            a0 = fmaf(h0.x, w[k], a0);     a1 = fmaf(h0.y, w[k + 1], a1);
            a0 = fmaf(h0.z, w[k + 2], a0); a1 = fmaf(h0.w, w[k + 3], a1);
            a2 = fmaf(h1.x, w[k], a2);     a3 = fmaf(h1.y, w[k + 1], a3);
            a2 = fmaf(h1.z, w[k + 2], a2); a3 = fmaf(h1.w, w[k + 3], a3);
        }
        out_s[r * 64 + c]  = a0 + a1;
        out_s[r2 * 64 + c] = a2 + a3;
    }
}

// ---------------- fused layer: GCN + GAT + residual + LN, one graph/block ----------------
#define LAY_SMEM ((2 * NH + 64 * 68 + N_ * 4) * 4)
__global__ void k_layer(const float* __restrict__ hin, const float* __restrict__ Wg,
                        const float* __restrict__ bg, const float* __restrict__ Wa,
                        const float* __restrict__ attS, const float* __restrict__ attD,
                        const float* __restrict__ ba, const float* __restrict__ lng,
                        const float* __restrict__ lnb, float* __restrict__ hout) {
    extern __shared__ __align__(16) float sm[];
    float* A      = sm;                     // h -> g -> per-warp GAT scratch
    float* Bm     = sm + NH;                // hw -> gh
    float* WsT    = sm + 2 * NH;
    float* asrc_s = sm + 2 * NH + 64 * 68;
    int g = blockIdx.x, tid = threadIdx.x;
    int lane = tid & 31, w = tid >> 5;

    const float* hrow = hin + (size_t)g * NH;
    for (int i = tid * 4; i < NH; i += 2048)
        *(float4*)&A[i] = *(const float4*)&hrow[i];
    for (int i = tid; i < 4096; i += 512)
        WsT[(i & 63) * 68 + (i >> 6)] = Wg[i];
    __syncthreads();
    gemm_block(A, WsT, Bm, tid);            // Bm = h @ Wg
    __syncthreads();

    // ---- GCN aggregate (direct CSR reads), write g in place over A ----
    {
        float bx = bg[2 * lane], by = bg[2 * lane + 1];
        for (int d = w; d < N_; d += 16) {
            int p0 = d_csr_ptr[d], p1 = d_csr_ptr[d + 1];
            float2 a0 = {0.f, 0.f}, a1 = {0.f, 0.f}, a2 = {0.f, 0.f}, a3 = {0.f, 0.f};
            int p = p0;
            for (; p + 4 <= p1; p += 4) {
                float2 s0 = d_csr_sg[p],     s1 = d_csr_sg[p + 1];
                float2 s2 = d_csr_sg[p + 2], s3 = d_csr_sg[p + 3];
                float2 v0 = *(const float2*)&Bm[__float_as_int(s0.x) * 64 + 2 * lane];
                float2 v1 = *(const float2*)&Bm[__float_as_int(s1.x) * 64 + 2 * lane];
                float2 v2 = *(const float2*)&Bm[__float_as_int(s2.x) * 64 + 2 * lane];
                float2 v3 = *(const float2*)&Bm[__float_as_int(s3.x) * 64 + 2 * lane];
                a0.x = fmaf(s0.y, v0.x, a0.x); a0.y = fmaf(s0.y, v0.y, a0.y);
                a1.x = fmaf(s1.y, v1.x, a1.x); a1.y = fmaf(s1.y, v1.y, a1.y);
                a2.x = fmaf(s2.y, v2.x, a2.x); a2.y = fmaf(s2.y, v2.y, a2.y);
                a3.x = fmaf(s3.y, v3.x, a3.x); a3.y = fmaf(s3.y, v3.y, a3.y);
            }
            for (; p < p1; p++) {
                float2 s0 = d_csr_sg[p];
                float2 v0 = *(const float2*)&Bm[__float_as_int(s0.x) * 64 + 2 * lane];
                a0.x = fmaf(s0.y, v0.x, a0.x); a0.y = fmaf(s0.y, v0.y, a0.y);
            }
            float gx = (a0.x + a1.x) + (a2.x + a3.x) + bx;
            float gy = (a0.y + a1.y) + (a2.y + a3.y) + by;
            A[d * 64 + 2 * lane]     = gelu_f(gx);
            A[d * 64 + 2 * lane + 1] = gelu_f(gy);
        }
    }
    __syncthreads();
    for (int i = tid; i < 4096; i += 512)
        WsT[(i & 63) * 68 + (i >> 6)] = Wa[i];
    __syncthreads();
    gemm_block(A, WsT, Bm, tid);            // Bm = g @ Wa
    __syncthreads();

    // ---- attention scores ----
    int hh = lane >> 3;
    float wsl = attS[lane], wsl2 = attS[lane + 32];
    float wdl = attD[lane], wdl2 = attD[lane + 32];
    for (int n = w; n < N_; n += 16) {
        float r1 = Bm[n * 64 + lane] * wsl;
        float r2 = Bm[n * 64 + 32 + lane] * wsl2;
        #pragma unroll
        for (int off = 8; off; off >>= 1) {
            r1 += __shfl_xor_sync(~0u, r1, off, 16);
            r2 += __shfl_xor_sync(~0u, r2, off, 16);
        }
        if (lane == 0)       { asrc_s[n * 4 + 0] = r1; asrc_s[n * 4 + 2] = r2; }
        else if (lane == 16) { asrc_s[n * 4 + 1] = r1; asrc_s[n * 4 + 3] = r2; }
    }
    __syncthreads();

    float* scrA = A + w * 1480;
    int*   scrS = (int*)(scrA + DCAP * 4);
    float bx  = ba[2 * lane],  by  = ba[2 * lane + 1];
    float gsx = lng[2 * lane], gsy = lng[2 * lane + 1];
    float gbx = lnb[2 * lane], gby = lnb[2 * lane + 1];

    for (int d = w; d < N_; d += 16) {
        float r1 = Bm[d * 64 + lane] * wdl;
        float r2 = Bm[d * 64 + 32 + lane] * wdl2;
        #pragma unroll
        for (int off = 8; off; off >>= 1) {
            r1 += __shfl_xor_sync(~0u, r1, off, 16);
            r2 += __shfl_xor_sync(~0u, r2, off, 16);
        }
        float h0 = __shfl_sync(~0u, r1, 0),  h1 = __shfl_sync(~0u, r1, 16);
        float h2 = __shfl_sync(~0u, r2, 0),  h3 = __shfl_sync(~0u, r2, 16);

        int p0 = d_csr_ptr[d], deg = d_csr_ptr[d + 1] - p0;
        float2 acc = {0.f, 0.f};
        float invh;
        if (deg <= DCAP) {
            float m0 = -1e30f, m1 = -1e30f, m2 = -1e30f, m3 = -1e30f;
            for (int j = lane; j < deg; j += 32) {
                float2 sgv = d_csr_sg[p0 + j];
                int s = __float_as_int(sgv.x);
                float4 av = *(const float4*)&asrc_s[s * 4];
                float a0 = av.x + h0, a1 = av.y + h1, a2 = av.z + h2, a3 = av.w + h3;
                a0 = fmaxf(a0, 0.2f * a0); a1 = fmaxf(a1, 0.2f * a1);
                a2 = fmaxf(a2, 0.2f * a2); a3 = fmaxf(a3, 0.2f * a3);
                scrA[j * 4 + 0] = a0; scrA[j * 4 + 1] = a1;
                scrA[j * 4 + 2] = a2; scrA[j * 4 + 3] = a3;
                scrS[j] = s;
                m0 = fmaxf(m0, a0); m1 = fmaxf(m1, a1);
                m2 = fmaxf(m2, a2); m3 = fmaxf(m3, a3);
            }
            #pragma unroll
            for (int off = 16; off; off >>= 1) {
                m0 = fmaxf(m0, __shfl_xor_sync(~0u, m0, off));
                m1 = fmaxf(m1, __shfl_xor_sync(~0u, m1, off));
                m2 = fmaxf(m2, __shfl_xor_sync(~0u, m2, off));
                m3 = fmaxf(m3, __shfl_xor_sync(~0u, m3, off));
            }
            __syncwarp();
            float d0 = 0.f, d1 = 0.f, d2 = 0.f, d3 = 0.f;
            for (int j = lane; j < deg; j += 32) {
                float e0 = __expf(scrA[j * 4 + 0] - m0);
                float e1 = __expf(scrA[j * 4 + 1] - m1);
                float e2 = __expf(scrA[j * 4 + 2] - m2);
                float e3 = __expf(scrA[j * 4 + 3] - m3);
                scrA[j * 4 + 0] = e0; scrA[j * 4 + 1] = e1;
                scrA[j * 4 + 2] = e2; scrA[j * 4 + 3] = e3;
                d0 += e0; d1 += e1; d2 += e2; d3 += e3;
            }
            #pragma unroll
            for (int off = 16; off; off >>= 1) {
                d0 += __shfl_xor_sync(~0u, d0, off);
                d1 += __shfl_xor_sync(~0u, d1, off);
                d2 += __shfl_xor_sync(~0u, d2, off);
                d3 += __shfl_xor_sync(~0u, d3, off);
            }
            invh = 1.0f / ((hh == 0) ? d0 : (hh == 1) ? d1 : (hh == 2) ? d2 : d3);
            __syncwarp();
            float2 acc2 = {0.f, 0.f};
            int j = 0;
            for (; j + 2 <= deg; j += 2) {
                float al0 = scrA[j * 4 + hh], al1 = scrA[(j + 1) * 4 + hh];
                int s0v = scrS[j], s1v = scrS[j + 1];
                float2 v0 = *(const float2*)&Bm[s0v * 64 + 2 * lane];
                float2 v1 = *(const float2*)&Bm[s1v * 64 + 2 * lane];
                acc.x  = fmaf(al0, v0.x, acc.x);  acc.y  = fmaf(al0, v0.y, acc.y);
                acc2.x = fmaf(al1, v1.x, acc2.x); acc2.y = fmaf(al1, v1.y, acc2.y);
            }
            if (j < deg) {
                float al = scrA[j * 4 + hh];
                float2 v = *(const float2*)&Bm[scrS[j] * 64 + 2 * lane];
                acc.x = fmaf(al, v.x, acc.x); acc.y = fmaf(al, v.y, acc.y);
            }
            acc.x += acc2.x; acc.y += acc2.y;
        } else {
            float adh = (hh == 0) ? h0 : (hh == 1) ? h1 : (hh == 2) ? h2 : h3;
            float m = -1e30f;
            for (int p = p0; p < p0 + deg; p++) {
                float a = asrc_s[__float_as_int(d_csr_sg[p].x) * 4 + hh] + adh;
                a = fmaxf(a, 0.2f * a);
                m = fmaxf(m, a);
            }
            float den = 0.f;
            for (int p = p0; p < p0 + deg; p++) {
                int s = __float_as_int(d_csr_sg[p].x);
                float a = asrc_s[s * 4 + hh] + adh;
                a = fmaxf(a, 0.2f * a);
                float e = __expf(a - m);
                den += e;
                float2 v = *(const float2*)&Bm[s * 64 + 2 * lane];
                acc.x = fmaf(e, v.x, acc.x); acc.y = fmaf(e, v.y, acc.y);
            }
            invh = 1.0f / den;
        }
        float rx = acc.x * invh + bx + hin[((size_t)g * N_ + d) * 64 + 2 * lane];
        float ry = acc.y * invh + by + hin[((size_t)g * N_ + d) * 64 + 2 * lane + 1];
        float s1 = rx + ry, s2 = rx * rx + ry * ry;
        #pragma unroll
        for (int off = 16; off; off >>= 1) {
            s1 += __shfl_xor_sync(~0u, s1, off);
            s2 += __shfl_xor_sync(~0u, s2, off);
        }
        float mu = s1 * (1.0f / 64.0f);
        float var = fmaxf(s2 * (1.0f / 64.0f) - mu * mu, 0.0f);
        float inv = rsqrtf(var + 1e-5f);
        *(float2*)&hout[((size_t)g * N_ + d) * 64 + 2 * lane] =
            make_float2((rx - mu) * inv * gsx + gbx, (ry - mu) * inv * gsy + gby);
    }
}

// ------- fused 3-layer temporal conv, splatted f32x2, 5 bn x 640 threads -------
#define TC5_BN 5
#define TC5_THREADS 640
#define TC5_XS 2304
#define TC5_SMEM ((10240 + TC5_BN * TC5_XS) * 8)

__global__ void k_tconv3(const float* __restrict__ in_h, float* __restrict__ out,
                         const float* __restrict__ Wt_all, const float* __restrict__ bt_all) {
    extern __shared__ __align__(16) u64 smu[];
    u64* wsu = smu;
    u64* xs  = smu + 10240;
    int tid = threadIdx.x;
    int bn0 = blockIdx.x * TC5_BN;

    for (int i = tid; i < TC5_BN * TC5_XS; i += TC5_THREADS) xs[i] = 0ULL;
    __syncthreads();
    for (int idx = tid; idx < TC5_BN * 2048; idx += TC5_THREADS) {
        int bnL = idx >> 11, r = idx & 2047, bn = bn0 + bnL;
        int tt = r >> 6, ch = r & 63;
        int b = bn / N_, n = bn % N_;
        float v = in_h[(((size_t)(b * 32 + tt) * N_) + n) * 64 + ch];
        xs[bnL * TC5_XS + ch * 36 + 2 + tt] = pk2(v, v);
    }

    int bnL = tid / 128, t7 = tid % 128;
    int op = t7 & 31, t0 = (t7 >> 5) * 8;
    int ch0 = 2 * op, ch1 = 2 * op + 1;
    u64* xb = xs + bnL * TC5_XS;

    for (int p = 0; p < 3; p++) {
        __syncthreads();
        const float* W = Wt_all + p * 20480;
        for (int i = tid; i < 10240; i += TC5_THREADS) {
            int opx = i & 31, r = i >> 5;
            wsu[r * 32 + opx] = pk2(W[(2 * opx) * 320 + r], W[(2 * opx + 1) * 320 + r]);
        }
        __syncthreads();

        u64 bp = pk2(bt_all[p * 64 + ch0], bt_all[p * 64 + ch1]);
        u64 acc2[8];
        #pragma unroll
        for (int u = 0; u < 8; u++) acc2[u] = bp;

        for (int i = 0; i < 64; i++) {
            const u64* xi = xb + i * 36 + t0;
            u64 win[12];
            #pragma unroll
            for (int j = 0; j < 12; j++) win[j] = xi[j];
            const u64* wr = wsu + (i * 5) * 32 + op;
            u64 w0 = wr[0], w1 = wr[32], w2 = wr[64], w3 = wr[96], w4 = wr[128];
            #pragma unroll
            for (int u = 0; u < 8; u++) {
                u64 a = acc2[u];
                a = fma2(win[u],     w0, a);
                a = fma2(win[u + 1], w1, a);
                a = fma2(win[u + 2], w2, a);
                a = fma2(win[u + 3], w3, a);
                a = fma2(win[u + 4], w4, a);
                acc2[u] = a;
            }
        }
        __syncthreads();

        if (p < 2) {
            #pragma unroll
            for (int u = 0; u < 8; u++) {
                float a, b;
                upk2(acc2[u], a, b);
                int t = t0 + u;
                float x0, x1, dum;
                upk2(xb[ch0 * 36 + 2 + t], x0, dum);
                upk2(xb[ch1 * 36 + 2 + t], x1, dum);
                float n0 = gelu_f(a) + x0;
                float n1 = gelu_f(b) + x1;
                xb[ch0 * 36 + 2 + t] = pk2(n0, n0);
                xb[ch1 * 36 + 2 + t] = pk2(n1, n1);
            }
        } else {
            int bn = bn0 + bnL;
            float* ob = out + (size_t)bn * 2048;
            #pragma unroll
            for (int u = 0; u < 8; u++) {
                float a, b;
                upk2(acc2[u], a, b);
                int t = t0 + u;
                float x0, x1, dum;
                upk2(xb[ch0 * 36 + 2 + t], x0, dum);
                upk2(xb[ch1 * 36 + 2 + t], x1, dum);
                ob[ch0 * 32 + t] = gelu_f(a) + x0;
                ob[ch1 * 32 + t] = gelu_f(b) + x1;
            }
        }
    }
}

// ---------------- MLP1 split-K (scalar) ----------------
#define ZS_STRIDE 65
#define MLP1_SMEM ((G_ * ZS_STRIDE + 64 * 256) * 4)
__global__ void k_mlp1(const float* __restrict__ xt, const float* __restrict__ W1) {
    extern __shared__ __align__(16) float sm[];
    float* zs  = sm;
    float* w1s = sm + G_ * ZS_STRIDE;
    int n = blockIdx.x, tid = threadIdx.x;
    for (int i = tid; i < 8192; i += 256) {
        int b = i >> 11, c = (i >> 5) & 63, t = i & 31;
        zs[(b * 32 + t) * ZS_STRIDE + c] = xt[(((size_t)(b * N_ + n)) * 64 + c) * 32 + t];
    }
    for (int i = tid; i < 16384; i += 256)
        w1s[i] = W1[(size_t)n * 16384 + i];
    __syncthreads();
    int ow = tid & 31, gw = tid >> 5, o0 = ow * 8;
    float* pb = d_part + (size_t)n * (G_ * 256);
    for (int pass = 0; pass < 4; pass++) {
        int g0 = pass * 32 + gw * 4;
        float acc[4][8] = {};
        #pragma unroll 4
        for (int k = 0; k < 64; k++) {
            float4 wa = *(const float4*)&w1s[k * 256 + o0];
            float4 wb = *(const float4*)&w1s[k * 256 + o0 + 4];
            float wv[8] = {wa.x, wa.y, wa.z, wa.w, wb.x, wb.y, wb.z, wb.w};
            float z[4];
            #pragma unroll
            for (int j = 0; j < 4; j++) z[j] = zs[(g0 + j) * ZS_STRIDE + k];
            #pragma unroll
            for (int j = 0; j < 4; j++)
                #pragma unroll
                for (int q = 0; q < 8; q++)
                    acc[j][q] = fmaf(z[j], wv[q], acc[j][q]);
        }
        #pragma unroll
        for (int j = 0; j < 4; j++) {
            *(float4*)&pb[(g0 + j) * 256 + o0]     = make_float4(acc[j][0], acc[j][1], acc[j][2], acc[j][3]);
            *(float4*)&pb[(g0 + j) * 256 + o0 + 4] = make_float4(acc[j][4], acc[j][5], acc[j][6], acc[j][7]);
        }
    }
}

__global__ void k_redmlp2(const float* __restrict__ b1, const float* __restrict__ W2,
                          const float* __restrict__ b2, float* __restrict__ out) {
    __shared__ float hid[256];
    int g = blockIdx.x, o = threadIdx.x;
    float a0 = 0.f, a1 = 0.f;
    size_t base = (size_t)g * 256 + o;
    int nb = 0;
    for (; nb + 2 <= N_; nb += 2) {
        a0 += d_part[(size_t)nb * (G_ * 256) + base];
        a1 += d_part[(size_t)(nb + 1) * (G_ * 256) + base];
    }
    for (; nb < N_; nb++) a0 += d_part[(size_t)nb * (G_ * 256) + base];
    hid[o] = gelu_f(a0 + a1 + b1[o]);
    __syncthreads();
    if (o < 64) {
        float acc = b2[o];
        #pragma unroll 8
        for (int k = 0; k < 256; k++) acc = fmaf(hid[k], W2[k * 64 + o], acc);
        out[(size_t)g * 64 + o] = acc;
    }
}

extern "C" void kernel_launch(void* const* d_in, const int* in_sizes, int n_in,
                              void* d_out, int out_size) {
    float* out = (float*)d_out;
    static cudaStream_t s2 = nullptr;
    static cudaEvent_t evFork = nullptr, evX = nullptr, evJoin = nullptr;
    if (s2 == nullptr) {
        cudaStreamCreateWithFlags(&s2, cudaStreamNonBlocking);
        cudaEventCreateWithFlags(&evFork, cudaEventDisableTiming);
        cudaEventCreateWithFlags(&evX,    cudaEventDisableTiming);
        cudaEventCreateWithFlags(&evJoin, cudaEventDisableTiming);
        cudaFuncSetAttribute(k_layer,  cudaFuncAttributeMaxDynamicSharedMemorySize, LAY_SMEM);
        cudaFuncSetAttribute(k_tconv3, cudaFuncAttributeMaxDynamicSharedMemorySize, TC5_SMEM);
        cudaFuncSetAttribute(k_mlp1,   cudaFuncAttributeMaxDynamicSharedMemorySize, MLP1_SMEM);
    }

    cudaEventRecord(evFork, 0);
    cudaStreamWaitEvent(s2, evFork, 0);
    cudaMemcpyToSymbolAsync(d_xin, d_in[0], (size_t)GN * H_ * 4, 0, cudaMemcpyDeviceToDevice, s2);
    cudaEventRecord(evX, s2);
    cudaMemcpyToSymbolAsync(d_W1c, d_in[13], (size_t)NH * 256 * 4, 0, cudaMemcpyDeviceToDevice, s2);
    k_stageB<<<48, 256, 0, s2>>>((const float*)d_in[9], (const float*)d_in[10],
                                 (const float*)d_in[14], (const float*)d_in[15],
                                 (const float*)d_in[16]);
    cudaEventRecord(evJoin, s2);

    k_stageA<<<64, 256>>>((const int*)d_in[1], (const float*)d_in[2],
                          (const float*)d_in[3], (const float*)d_in[4],
                          (const float*)d_in[5], (const float*)d_in[6],
                          (const float*)d_in[7], (const float*)d_in[8],
                          (const float*)d_in[11], (const float*)d_in[12]);
    k_prepAll<<<1, CHUNK_>>>();
    cudaStreamWaitEvent(0, evX, 0);

    float *xin, *Wg, *bg, *Wa, *asw, *adw, *ba, *Wt, *bt, *lng, *lnb, *W1, *b1, *W2, *b2;
    float *hbuf, *xt0;
    cudaGetSymbolAddress((void**)&xin,  d_xin);
    cudaGetSymbolAddress((void**)&Wg,   d_Wg);
    cudaGetSymbolAddress((void**)&bg,   d_bg);
    cudaGetSymbolAddress((void**)&Wa,   d_Wa);
    cudaGetSymbolAddress((void**)&asw,  d_asw);
    cudaGetSymbolAddress((void**)&adw,  d_adw);
    cudaGetSymbolAddress((void**)&ba,   d_ba);
    cudaGetSymbolAddress((void**)&Wt,   d_Wt);
    cudaGetSymbolAddress((void**)&bt,   d_bt);
    cudaGetSymbolAddress((void**)&lng,  d_lngc);
    cudaGetSymbolAddress((void**)&lnb,  d_lnbc);
    cudaGetSymbolAddress((void**)&W1,   d_W1c);
    cudaGetSymbolAddress((void**)&b1,   d_b1c);
    cudaGetSymbolAddress((void**)&W2,   d_W2c);
    cudaGetSymbolAddress((void**)&b2,   d_b2c);
    cudaGetSymbolAddress((void**)&hbuf, d_h);
    cudaGetSymbolAddress((void**)&xt0,  d_xt0);

    const float* hin = xin;
    for (int l = 0; l < 3; l++) {
        k_layer<<<G_, 512, LAY_SMEM>>>(hin, Wg + l * 4096, bg + l * 64, Wa + l * 4096,
                                       asw + l * 64, adw + l * 64, ba + l * 64,
                                       lng + l * 64, lnb + l * 64, hbuf);
        hin = hbuf;
    }

    cudaStreamWaitEvent(0, evJoin, 0);
    k_tconv3<<<(B_ * N_) / TC5_BN, TC5_THREADS, TC5_SMEM>>>(hbuf, xt0, Wt, bt);

    k_mlp1<<<N_, 256, MLP1_SMEM>>>(xt0, W1);
    k_redmlp2<<<G_, 256>>>(b1, W2, b2, out);
}

// round 12
// speedup vs baseline: 1.0527x; 1.0527x over previous
#include <cuda_runtime.h>
#include <math.h>

#define B_   4
#define T_   32
#define N_   370
#define E_   11840
#define E2_  (E_ + N_)
#define G_   128
#define H_   64
#define GN   (G_ * N_)
#define NH   (N_ * H_)
#define CHUNK_ 512
#define DCAP 256

typedef unsigned long long u64;
__device__ __forceinline__ u64 pk2(float lo, float hi) {
    u64 r; asm("mov.b64 %0,{%1,%2};" : "=l"(r) : "f"(lo), "f"(hi)); return r;
}
__device__ __forceinline__ void upk2(u64 v, float& lo, float& hi) {
    asm("mov.b64 {%0,%1},%2;" : "=f"(lo), "=f"(hi) : "l"(v));
}
__device__ __forceinline__ u64 fma2(u64 a, u64 b, u64 c) {
    u64 d; asm("fma.rn.f32x2 %0,%1,%2,%3;" : "=l"(d) : "l"(a), "l"(b), "l"(c)); return d;
}

__device__ float d_xin[GN * H_];
__device__ int   d_eic[2 * E_];
__device__ float d_ewc[E_];
__device__ float d_Wg[3 * 4096];
__device__ float d_bg[3 * 64];
__device__ float d_Wa[3 * 4096];
__device__ float d_asw[3 * 64];
__device__ float d_adw[3 * 64];
__device__ float d_ba[3 * 64];
__device__ float d_Wt[3 * 20480];
__device__ float d_bt[3 * 64];
__device__ float d_lngc[3 * 64];
__device__ float d_lnbc[3 * 64];
__device__ float d_W1c[NH * 256];
__device__ float d_b1c[256];
__device__ float d_W2c[256 * 64];
__device__ float d_b2c[64];

__device__ float  d_h[GN * H_];
__device__ float  d_bufA[GN * H_];
__device__ int    d_csr_ptr[N_ + 1];
__device__ int    d_csr_eid[E2_];
__device__ int    d_csr_dst[E2_];
__device__ float2 d_csr_sg[E2_];      // {src*64 (bits), gnorm}
__device__ int    d_cnt[CHUNK_ * N_];
__device__ float  d_xt0[B_ * N_ * H_ * T_];
__device__ float  d_part[N_ * G_ * 256];

__device__ __forceinline__ float gelu_f(float x) {
    return 0.5f * x * (1.0f + erff(x * 0.70710678118654752f));
}

// ---------------- staging ----------------
__global__ void k_stageA(const int* ei, const float* ew, const float* Wg,
                         const float* bg, const float* Wa, const float* asw,
                         const float* adw, const float* ba, const float* lng,
                         const float* lnb) {
    int i0 = blockIdx.x * 256 + threadIdx.x, st = gridDim.x * 256;
    for (int i = i0; i < 2 * E_; i += st) d_eic[i] = ei[i];
    for (int i = i0; i < E_;    i += st) d_ewc[i] = ew[i];
    for (int i = i0; i < 12288; i += st) { d_Wg[i] = Wg[i]; d_Wa[i] = Wa[i]; }
    for (int i = i0; i < CHUNK_ * N_; i += st) d_cnt[i] = 0;
    for (int i = i0; i < 192;   i += st) {
        d_bg[i] = bg[i]; d_asw[i] = asw[i]; d_adw[i] = adw[i];
        d_ba[i] = ba[i]; d_lngc[i] = lng[i]; d_lnbc[i] = lnb[i];
    }
}
__global__ void k_stageB(const float* Wt, const float* bt, const float* b1,
                         const float* W2, const float* b2) {
    int i0 = blockIdx.x * 256 + threadIdx.x, st = gridDim.x * 256;
    for (int i = i0; i < 61440; i += st) d_Wt[i] = Wt[i];
    for (int i = i0; i < 192;   i += st) d_bt[i] = bt[i];
    for (int i = i0; i < 256;   i += st) d_b1c[i] = b1[i];
    for (int i = i0; i < 16384; i += st) d_W2c[i] = W2[i];
    for (int i = i0; i < 64;    i += st) d_b2c[i] = b2[i];
}

// ---------------- prep: CSR + deg + gnorm, one block ----------------
__global__ void k_prepAll() {
    int t = threadIdx.x;
    const int* dsts = d_eic + E_;
    const int EC = (E_ + CHUNK_ - 1) / CHUNK_;
    int e0 = t * EC, e1 = min(e0 + EC, E_);
    __shared__ int   ptr_s[N_ + 1];
    __shared__ float dis_s[N_];
    for (int e = e0; e < e1; e++) d_cnt[t * N_ + dsts[e]]++;
    __syncthreads();
    if (t < N_) {
        int run = 0;
        for (int c = 0; c < CHUNK_; c++) {
            int idx = c * N_ + t;
            int v = d_cnt[idx]; d_cnt[idx] = run; run += v;
        }
        ptr_s[t] = run + 1;
    }
    __syncthreads();
    if (t == 0) {
        int p = 0;
        for (int n = 0; n < N_; n++) { int v = ptr_s[n]; ptr_s[n] = p; p += v; }
        ptr_s[N_] = p;
    }
    __syncthreads();
    if (t <= N_) d_csr_ptr[t] = ptr_s[t];
    for (int e = e0; e < e1; e++) {
        int d = dsts[e];
        int pos = ptr_s[d] + d_cnt[t * N_ + d]++;
        d_csr_eid[pos] = e; d_csr_dst[pos] = d;
    }
    __syncthreads();
    if (t < N_) {
        int pos = ptr_s[t + 1] - 1;
        d_csr_eid[pos] = E_ + t; d_csr_dst[pos] = t;
    }
    __syncthreads();
    for (int n = t; n < N_; n += CHUNK_) {
        float s = 1.0f;
        for (int p = ptr_s[n]; p < ptr_s[n + 1] - 1; p++) s += d_ewc[d_csr_eid[p]];
        dis_s[n] = rsqrtf(s);
    }
    __syncthreads();
    for (int pos = t; pos < E2_; pos += CHUNK_) {
        int e = d_csr_eid[pos], d = d_csr_dst[pos];
        float dd = dis_s[d];
        int s; float gn;
        if (e < E_) { s = d_eic[e]; gn = dis_s[s] * d_ewc[e] * dd; }
        else        { s = d;        gn = dd * dd; }
        d_csr_sg[pos] = make_float2(__int_as_float(s * 64), gn);   // pre-scaled
    }
}

// ------- in-block 370x64 @ 64x64 GEMM (512 threads), scalar FFMA -------
__device__ __forceinline__ void gemm_block(const float* __restrict__ in_s,
                                           const float* __restrict__ WsT,
                                           float* __restrict__ out_s, int tid) {
    int c = tid & 63, rb = tid >> 6;
    const float* wc = WsT + c * 68;
    float w[64];
    #pragma unroll
    for (int k = 0; k < 64; k += 4) *(float4*)&w[k] = *(const float4*)&wc[k];
    for (int r = rb; r < 185; r += 8) {
        int r2 = r + 185;
        float a0 = 0.f, a1 = 0.f, a2 = 0.f, a3 = 0.f;
        #pragma unroll
        for (int k = 0; k < 64; k += 4) {
            float4 h0 = *(const float4*)&in_s[r * 64 + k];
            float4 h1 = *(const float4*)&in_s[r2 * 64 + k];
            a0 = fmaf(h0.x, w[k], a0);     a1 = fmaf(h0.y, w[k + 1], a1);
            a0 = fmaf(h0.z, w[k + 2], a0); a1 = fmaf(h0.w, w[k + 3], a1);
            a2 = fmaf(h1.x, w[k], a2);     a3 = fmaf(h1.y, w[k + 1], a3);
            a2 = fmaf(h1.z, w[k + 2], a2); a3 = fmaf(h1.w, w[k + 3], a3);
        }
        out_s[r * 64 + c]  = a0 + a1;
        out_s[r2 * 64 + c] = a2 + a3;
    }
}

// ---------------- K1: GCN layer ----------------
#define GCN_SMEM ((2 * NH + 64 * 68) * 4)
__global__ void k_gcn(const float* __restrict__ hin, const float* __restrict__ Wg,
                      const float* __restrict__ bg, float* __restrict__ gout) {
    extern __shared__ __align__(16) float sm[];
    float* h_s  = sm;
    float* hw_s = sm + NH;
    float* WsT  = sm + 2 * NH;
    int g = blockIdx.x, tid = threadIdx.x;
    const float* hrow = hin + (size_t)g * NH;
    for (int i = tid * 4; i < NH; i += 2048)
        *(float4*)&h_s[i] = *(const float4*)&hrow[i];
    for (int i = tid; i < 4096; i += 512)
        WsT[(i & 63) * 68 + (i >> 6)] = Wg[i];
    __syncthreads();
    gemm_block(h_s, WsT, hw_s, tid);
    __syncthreads();

    int lane = tid & 31, w = tid >> 5;
    float2* scr = (float2*)(h_s + w * 1480);
    float bx = bg[2 * lane], by = bg[2 * lane + 1];
    for (int d = w; d < N_; d += 16) {
        int p0 = d_csr_ptr[d], deg = d_csr_ptr[d + 1] - p0;
        float2 acc = make_float2(0.f, 0.f);
        for (int j = lane; j < deg; j += 32) scr[j] = d_csr_sg[p0 + j];
        __syncwarp();
        int j = 0;
        for (; j + 2 <= deg; j += 2) {
            float2 s0 = scr[j], s1 = scr[j + 1];
            float2 v0 = *(const float2*)&hw_s[__float_as_int(s0.x) + 2 * lane];
            float2 v1 = *(const float2*)&hw_s[__float_as_int(s1.x) + 2 * lane];
            acc.x = fmaf(s0.y, v0.x, acc.x); acc.y = fmaf(s0.y, v0.y, acc.y);
            acc.x = fmaf(s1.y, v1.x, acc.x); acc.y = fmaf(s1.y, v1.y, acc.y);
        }
        if (j < deg) {
            float2 s0 = scr[j];
            float2 v0 = *(const float2*)&hw_s[__float_as_int(s0.x) + 2 * lane];
            acc.x = fmaf(s0.y, v0.x, acc.x); acc.y = fmaf(s0.y, v0.y, acc.y);
        }
        __syncwarp();
        *(float2*)&gout[((size_t)g * N_ + d) * 64 + 2 * lane] =
            make_float2(gelu_f(acc.x + bx), gelu_f(acc.y + by));
    }
}

// ---------------- K2: GAT + residual + LN ----------------
#define GAT2_SMEM ((2 * NH + 64 * 68 + N_ * 4) * 4)
__global__ void k_gat2(const float* __restrict__ gin, const float* __restrict__ Wa,
                       const float* __restrict__ attS, const float* __restrict__ attD,
                       const float* __restrict__ ba, const float* __restrict__ lng,
                       const float* __restrict__ lnb, const float* __restrict__ hin,
                       float* __restrict__ hout) {
    extern __shared__ __align__(16) float sm[];
    float* g_s    = sm;
    float* gh_s   = sm + NH;
    float* WsT    = sm + 2 * NH;
    float* asrc_s = sm + 2 * NH + 64 * 68;
    int g = blockIdx.x, tid = threadIdx.x;
    const float* grow = gin + (size_t)g * NH;
    for (int i = tid * 4; i < NH; i += 2048)
        *(float4*)&g_s[i] = *(const float4*)&grow[i];
    for (int i = tid; i < 4096; i += 512)
        WsT[(i & 63) * 68 + (i >> 6)] = Wa[i];
    __syncthreads();
    gemm_block(g_s, WsT, gh_s, tid);
    __syncthreads();

    int lane = tid & 31, w = tid >> 5, hh = lane >> 3;
    float wsl = attS[lane], wsl2 = attS[lane + 32];
    float wdl = attD[lane], wdl2 = attD[lane + 32];
    for (int n = w; n < N_; n += 16) {
        float r1 = gh_s[n * 64 + lane] * wsl;
        float r2 = gh_s[n * 64 + 32 + lane] * wsl2;
        #pragma unroll
        for (int off = 8; off; off >>= 1) {
            r1 += __shfl_xor_sync(~0u, r1, off, 16);
            r2 += __shfl_xor_sync(~0u, r2, off, 16);
        }
        if (lane == 0)       { asrc_s[n * 4 + 0] = r1; asrc_s[n * 4 + 2] = r2; }
        else if (lane == 16) { asrc_s[n * 4 + 1] = r1; asrc_s[n * 4 + 3] = r2; }
    }
    __syncthreads();

    float* scrA = g_s + w * 1480;
    int*   scrS = (int*)(scrA + DCAP * 4);
    float bx  = ba[2 * lane],  by  = ba[2 * lane + 1];
    float gsx = lng[2 * lane], gsy = lng[2 * lane + 1];
    float gbx = lnb[2 * lane], gby = lnb[2 * lane + 1];

    for (int d = w; d < N_; d += 16) {
        float r1 = gh_s[d * 64 + lane] * wdl;
        float r2 = gh_s[d * 64 + 32 + lane] * wdl2;
        #pragma unroll
        for (int off = 8; off; off >>= 1) {
            r1 += __shfl_xor_sync(~0u, r1, off, 16);
            r2 += __shfl_xor_sync(~0u, r2, off, 16);
        }
        float h0 = __shfl_sync(~0u, r1, 0),  h1 = __shfl_sync(~0u, r1, 16);
        float h2 = __shfl_sync(~0u, r2, 0),  h3 = __shfl_sync(~0u, r2, 16);

        int p0 = d_csr_ptr[d], deg = d_csr_ptr[d + 1] - p0;
        float2 acc = {0.f, 0.f};
        float invh;
        if (deg <= DCAP) {
            float m0 = -1e30f, m1 = -1e30f, m2 = -1e30f, m3 = -1e30f;
            for (int j = lane; j < deg; j += 32) {
                float2 sgv = d_csr_sg[p0 + j];
                int soff = __float_as_int(sgv.x);              // src*64
                float4 av = *(const float4*)&asrc_s[soff >> 4];
                float a0 = av.x + h0, a1 = av.y + h1, a2 = av.z + h2, a3 = av.w + h3;
                a0 = fmaxf(a0, 0.2f * a0); a1 = fmaxf(a1, 0.2f * a1);
                a2 = fmaxf(a2, 0.2f * a2); a3 = fmaxf(a3, 0.2f * a3);
                scrA[j * 4 + 0] = a0; scrA[j * 4 + 1] = a1;
                scrA[j * 4 + 2] = a2; scrA[j * 4 + 3] = a3;
                scrS[j] = soff;
                m0 = fmaxf(m0, a0); m1 = fmaxf(m1, a1);
                m2 = fmaxf(m2, a2); m3 = fmaxf(m3, a3);
            }
            #pragma unroll
            for (int off = 16; off; off >>= 1) {
                m0 = fmaxf(m0, __shfl_xor_sync(~0u, m0, off));
                m1 = fmaxf(m1, __shfl_xor_sync(~0u, m1, off));
                m2 = fmaxf(m2, __shfl_xor_sync(~0u, m2, off));
                m3 = fmaxf(m3, __shfl_xor_sync(~0u, m3, off));
            }
            __syncwarp();
            float d0 = 0.f, d1 = 0.f, d2 = 0.f, d3 = 0.f;
            for (int j = lane; j < deg; j += 32) {
                float e0 = __expf(scrA[j * 4 + 0] - m0);
                float e1 = __expf(scrA[j * 4 + 1] - m1);
                float e2 = __expf(scrA[j * 4 + 2] - m2);
                float e3 = __expf(scrA[j * 4 + 3] - m3);
                scrA[j * 4 + 0] = e0; scrA[j * 4 + 1] = e1;
                scrA[j * 4 + 2] = e2; scrA[j * 4 + 3] = e3;
                d0 += e0; d1 += e1; d2 += e2; d3 += e3;
            }
            #pragma unroll
            for (int off = 16; off; off >>= 1) {
                d0 += __shfl_xor_sync(~0u, d0, off);
                d1 += __shfl_xor_sync(~0u, d1, off);
                d2 += __shfl_xor_sync(~0u, d2, off);
                d3 += __shfl_xor_sync(~0u, d3, off);
            }
            invh = 1.0f / ((hh == 0) ? d0 : (hh == 1) ? d1 : (hh == 2) ? d2 : d3);
            __syncwarp();
            float2 acc2 = {0.f, 0.f};
            int j = 0;
            for (; j + 2 <= deg; j += 2) {
                float al0 = scrA[j * 4 + hh], al1 = scrA[(j + 1) * 4 + hh];
                float2 v0 = *(const float2*)&gh_s[scrS[j] + 2 * lane];
                float2 v1 = *(const float2*)&gh_s[scrS[j + 1] + 2 * lane];
                acc.x  = fmaf(al0, v0.x, acc.x);  acc.y  = fmaf(al0, v0.y, acc.y);
                acc2.x = fmaf(al1, v1.x, acc2.x); acc2.y = fmaf(al1, v1.y, acc2.y);
            }
            if (j < deg) {
                float al = scrA[j * 4 + hh];
                float2 v = *(const float2*)&gh_s[scrS[j] + 2 * lane];
                acc.x = fmaf(al, v.x, acc.x); acc.y = fmaf(al, v.y, acc.y);
            }
            acc.x += acc2.x; acc.y += acc2.y;
        } else {
            float adh = (hh == 0) ? h0 : (hh == 1) ? h1 : (hh == 2) ? h2 : h3;
            float m = -1e30f;
            for (int p = p0; p < p0 + deg; p++) {
                float a = asrc_s[(__float_as_int(d_csr_sg[p].x) >> 4) + hh] + adh;
                a = fmaxf(a, 0.2f * a);
                m = fmaxf(m, a);
            }
            float den = 0.f;
            for (int p = p0; p < p0 + deg; p++) {
                int soff = __float_as_int(d_csr_sg[p].x);
                float a = asrc_s[(soff >> 4) + hh] + adh;
                a = fmaxf(a, 0.2f * a);
                float e = __expf(a - m);
                den += e;
                float2 v = *(const float2*)&gh_s[soff + 2 * lane];
                acc.x = fmaf(e, v.x, acc.x); acc.y = fmaf(e, v.y, acc.y);
            }
            invh = 1.0f / den;
        }
        float rx = acc.x * invh + bx + hin[((size_t)g * N_ + d) * 64 + 2 * lane];
        float ry = acc.y * invh + by + hin[((size_t)g * N_ + d) * 64 + 2 * lane + 1];
        float s1 = rx + ry, s2 = rx * rx + ry * ry;
        #pragma unroll
        for (int off = 16; off; off >>= 1) {
            s1 += __shfl_xor_sync(~0u, s1, off);
            s2 += __shfl_xor_sync(~0u, s2, off);
        }
        float mu = s1 * (1.0f / 64.0f);
        float var = fmaxf(s2 * (1.0f / 64.0f) - mu * mu, 0.0f);
        float inv = rsqrtf(var + 1e-5f);
        *(float2*)&hout[((size_t)g * N_ + d) * 64 + 2 * lane] =
            make_float2((rx - mu) * inv * gsx + gbx, (ry - mu) * inv * gsy + gby);
    }
}

// ------- fused 3-layer temporal conv, splatted f32x2, 5 bn x 640 threads -------
#define TC5_BN 5
#define TC5_THREADS 640
#define TC5_XS 2304
#define TC5_SMEM ((10240 + TC5_BN * TC5_XS) * 8)

__global__ void k_tconv3(const float* __restrict__ in_h, float* __restrict__ out,
                         const float* __restrict__ Wt_all, const float* __restrict__ bt_all) {
    extern __shared__ __align__(16) u64 smu[];
    u64* wsu = smu;
    u64* xs  = smu + 10240;
    int tid = threadIdx.x;
    int bn0 = blockIdx.x * TC5_BN;

    for (int i = tid; i < TC5_BN * TC5_XS; i += TC5_THREADS) xs[i] = 0ULL;
    __syncthreads();
    for (int idx = tid; idx < TC5_BN * 2048; idx += TC5_THREADS) {
        int bnL = idx >> 11, r = idx & 2047, bn = bn0 + bnL;
        int tt = r >> 6, ch = r & 63;
        int b = bn / N_, n = bn % N_;
        float v = in_h[(((size_t)(b * 32 + tt) * N_) + n) * 64 + ch];
        xs[bnL * TC5_XS + ch * 36 + 2 + tt] = pk2(v, v);
    }

    int bnL = tid / 128, t7 = tid % 128;
    int op = t7 & 31, t0 = (t7 >> 5) * 8;
    int ch0 = 2 * op, ch1 = 2 * op + 1;
    u64* xb = xs + bnL * TC5_XS;

    for (int p = 0; p < 3; p++) {
        __syncthreads();
        const float* W = Wt_all + p * 20480;
        for (int i = tid; i < 10240; i += TC5_THREADS) {
            int opx = i & 31, r = i >> 5;
            wsu[r * 32 + opx] = pk2(W[(2 * opx) * 320 + r], W[(2 * opx + 1) * 320 + r]);
        }
        __syncthreads();

        u64 bp = pk2(bt_all[p * 64 + ch0], bt_all[p * 64 + ch1]);
        u64 acc2[8];
        #pragma unroll
        for (int u = 0; u < 8; u++) acc2[u] = bp;

        for (int i = 0; i < 64; i++) {
            const u64* xi = xb + i * 36 + t0;
            u64 win[12];
            #pragma unroll
            for (int j = 0; j < 12; j++) win[j] = xi[j];
            const u64* wr = wsu + (i * 5) * 32 + op;
            u64 w0 = wr[0], w1 = wr[32], w2 = wr[64], w3 = wr[96], w4 = wr[128];
            #pragma unroll
            for (int u = 0; u < 8; u++) {
                u64 a = acc2[u];
                a = fma2(win[u],     w0, a);
                a = fma2(win[u + 1], w1, a);
                a = fma2(win[u + 2], w2, a);
                a = fma2(win[u + 3], w3, a);
                a = fma2(win[u + 4], w4, a);
                acc2[u] = a;
            }
        }
        __syncthreads();

        if (p < 2) {
            #pragma unroll
            for (int u = 0; u < 8; u++) {
                float a, b;
                upk2(acc2[u], a, b);
                int t = t0 + u;
                float x0, x1, dum;
                upk2(xb[ch0 * 36 + 2 + t], x0, dum);
                upk2(xb[ch1 * 36 + 2 + t], x1, dum);
                float n0 = gelu_f(a) + x0;
                float n1 = gelu_f(b) + x1;
                xb[ch0 * 36 + 2 + t] = pk2(n0, n0);
                xb[ch1 * 36 + 2 + t] = pk2(n1, n1);
            }
        } else {
            int bn = bn0 + bnL;
            float* ob = out + (size_t)bn * 2048;
            #pragma unroll
            for (int u = 0; u < 8; u++) {
                float a, b;
                upk2(acc2[u], a, b);
                int t = t0 + u;
                float x0, x1, dum;
                upk2(xb[ch0 * 36 + 2 + t], x0, dum);
                upk2(xb[ch1 * 36 + 2 + t], x1, dum);
                ob[ch0 * 32 + t] = gelu_f(a) + x0;
                ob[ch1 * 32 + t] = gelu_f(b) + x1;
            }
        }
    }
}

// ---------------- MLP1 split-K (scalar) ----------------
#define ZS_STRIDE 65
#define MLP1_SMEM ((G_ * ZS_STRIDE + 64 * 256) * 4)
__global__ void k_mlp1(const float* __restrict__ xt, const float* __restrict__ W1) {
    extern __shared__ __align__(16) float sm[];
    float* zs  = sm;
    float* w1s = sm + G_ * ZS_STRIDE;
    int n = blockIdx.x, tid = threadIdx.x;
    for (int i = tid; i < 8192; i += 256) {
        int b = i >> 11, c = (i >> 5) & 63, t = i & 31;
        zs[(b * 32 + t) * ZS_STRIDE + c] = xt[(((size_t)(b * N_ + n)) * 64 + c) * 32 + t];
    }
    for (int i = tid; i < 16384; i += 256)
        w1s[i] = W1[(size_t)n * 16384 + i];
    __syncthreads();
    int ow = tid & 31, gw = tid >> 5, o0 = ow * 8;
    float* pb = d_part + (size_t)n * (G_ * 256);
    for (int pass = 0; pass < 4; pass++) {
        int g0 = pass * 32 + gw * 4;
        float acc[4][8] = {};
        #pragma unroll 4
        for (int k = 0; k < 64; k++) {
            float4 wa = *(const float4*)&w1s[k * 256 + o0];
            float4 wb = *(const float4*)&w1s[k * 256 + o0 + 4];
            float wv[8] = {wa.x, wa.y, wa.z, wa.w, wb.x, wb.y, wb.z, wb.w};
            float z[4];
            #pragma unroll
            for (int j = 0; j < 4; j++) z[j] = zs[(g0 + j) * ZS_STRIDE + k];
            #pragma unroll
            for (int j = 0; j < 4; j++)
                #pragma unroll
                for (int q = 0; q < 8; q++)
                    acc[j][q] = fmaf(z[j], wv[q], acc[j][q]);
        }
        #pragma unroll
        for (int j = 0; j < 4; j++) {
            *(float4*)&pb[(g0 + j) * 256 + o0]     = make_float4(acc[j][0], acc[j][1], acc[j][2], acc[j][3]);
            *(float4*)&pb[(g0 + j) * 256 + o0 + 4] = make_float4(acc[j][4], acc[j][5], acc[j][6], acc[j][7]);
        }
    }
}

__global__ void k_redmlp2(const float* __restrict__ b1, const float* __restrict__ W2,
                          const float* __restrict__ b2, float* __restrict__ out) {
    __shared__ float hid[256];
    int g = blockIdx.x, o = threadIdx.x;
    float a0 = 0.f, a1 = 0.f;
    size_t base = (size_t)g * 256 + o;
    int nb = 0;
    for (; nb + 2 <= N_; nb += 2) {
        a0 += d_part[(size_t)nb * (G_ * 256) + base];
        a1 += d_part[(size_t)(nb + 1) * (G_ * 256) + base];
    }
    for (; nb < N_; nb++) a0 += d_part[(size_t)nb * (G_ * 256) + base];
    hid[o] = gelu_f(a0 + a1 + b1[o]);
    __syncthreads();
    if (o < 64) {
        float acc = b2[o];
        #pragma unroll 8
        for (int k = 0; k < 256; k++) acc = fmaf(hid[k], W2[k * 64 + o], acc);
        out[(size_t)g * 64 + o] = acc;
    }
}

extern "C" void kernel_launch(void* const* d_in, const int* in_sizes, int n_in,
                              void* d_out, int out_size) {
    float* out = (float*)d_out;
    static cudaStream_t s2 = nullptr;
    static cudaEvent_t evFork = nullptr, evX = nullptr, evJoin = nullptr;
    if (s2 == nullptr) {
        cudaStreamCreateWithFlags(&s2, cudaStreamNonBlocking);
        cudaEventCreateWithFlags(&evFork, cudaEventDisableTiming);
        cudaEventCreateWithFlags(&evX,    cudaEventDisableTiming);
        cudaEventCreateWithFlags(&evJoin, cudaEventDisableTiming);
        cudaFuncSetAttribute(k_gcn,    cudaFuncAttributeMaxDynamicSharedMemorySize, GCN_SMEM);
        cudaFuncSetAttribute(k_gat2,   cudaFuncAttributeMaxDynamicSharedMemorySize, GAT2_SMEM);
        cudaFuncSetAttribute(k_tconv3, cudaFuncAttributeMaxDynamicSharedMemorySize, TC5_SMEM);
        cudaFuncSetAttribute(k_mlp1,   cudaFuncAttributeMaxDynamicSharedMemorySize, MLP1_SMEM);
    }

    cudaEventRecord(evFork, 0);
    cudaStreamWaitEvent(s2, evFork, 0);
    cudaMemcpyToSymbolAsync(d_xin, d_in[0], (size_t)GN * H_ * 4, 0, cudaMemcpyDeviceToDevice, s2);
    cudaEventRecord(evX, s2);
    cudaMemcpyToSymbolAsync(d_W1c, d_in[13], (size_t)NH * 256 * 4, 0, cudaMemcpyDeviceToDevice, s2);
    k_stageB<<<48, 256, 0, s2>>>((const float*)d_in[9], (const float*)d_in[10],
                                 (const float*)d_in[14], (const float*)d_in[15],
                                 (const float*)d_in[16]);
    cudaEventRecord(evJoin, s2);

    k_stageA<<<64, 256>>>((const int*)d_in[1], (const float*)d_in[2],
                          (const float*)d_in[3], (const float*)d_in[4],
                          (const float*)d_in[5], (const float*)d_in[6],
                          (const float*)d_in[7], (const float*)d_in[8],
                          (const float*)d_in[11], (const float*)d_in[12]);
    k_prepAll<<<1, CHUNK_>>>();
    cudaStreamWaitEvent(0, evX, 0);

    float *xin, *Wg, *bg, *Wa, *asw, *adw, *ba, *Wt, *bt, *lng, *lnb, *W1, *b1, *W2, *b2;
    float *hbuf, *bufA, *xt0;
    cudaGetSymbolAddress((void**)&xin,  d_xin);
    cudaGetSymbolAddress((void**)&Wg,   d_Wg);
    cudaGetSymbolAddress((void**)&bg,   d_bg);
    cudaGetSymbolAddress((void**)&Wa,   d_Wa);
    cudaGetSymbolAddress((void**)&asw,  d_asw);
    cudaGetSymbolAddress((void**)&adw,  d_adw);
    cudaGetSymbolAddress((void**)&ba,   d_ba);
    cudaGetSymbolAddress((void**)&Wt,   d_Wt);
    cudaGetSymbolAddress((void**)&bt,   d_bt);
    cudaGetSymbolAddress((void**)&lng,  d_lngc);
    cudaGetSymbolAddress((void**)&lnb,  d_lnbc);
    cudaGetSymbolAddress((void**)&W1,   d_W1c);
    cudaGetSymbolAddress((void**)&b1,   d_b1c);
    cudaGetSymbolAddress((void**)&W2,   d_W2c);
    cudaGetSymbolAddress((void**)&b2,   d_b2c);
    cudaGetSymbolAddress((void**)&hbuf, d_h);
    cudaGetSymbolAddress((void**)&bufA, d_bufA);
    cudaGetSymbolAddress((void**)&xt0,  d_xt0);

    const float* hin = xin;
    for (int l = 0; l < 3; l++) {
        k_gcn<<<G_, 512, GCN_SMEM>>>(hin, Wg + l * 4096, bg + l * 64, bufA);
        k_gat2<<<G_, 512, GAT2_SMEM>>>(bufA, Wa + l * 4096, asw + l * 64, adw + l * 64,
                                       ba + l * 64, lng + l * 64, lnb + l * 64, hin, hbuf);
        hin = hbuf;
    }

    cudaStreamWaitEvent(0, evJoin, 0);
    k_tconv3<<<(B_ * N_) / TC5_BN, TC5_THREADS, TC5_SMEM>>>(hbuf, xt0, Wt, bt);

    k_mlp1<<<N_, 256, MLP1_SMEM>>>(xt0, W1);
    k_redmlp2<<<G_, 256>>>(b1, W2, b2, out);
}

// round 13
// speedup vs baseline: 1.0660x; 1.0126x over previous
#include <cuda_runtime.h>
#include <math.h>

#define B_   4
#define T_   32
#define N_   370
#define E_   11840
#define E2_  (E_ + N_)
#define G_   128
#define H_   64
#define GN   (G_ * N_)
#define NH   (N_ * H_)
#define CHUNK_ 512
#define DCAP 256

typedef unsigned long long u64;
__device__ __forceinline__ u64 pk2(float lo, float hi) {
    u64 r; asm("mov.b64 %0,{%1,%2};" : "=l"(r) : "f"(lo), "f"(hi)); return r;
}
__device__ __forceinline__ void upk2(u64 v, float& lo, float& hi) {
    asm("mov.b64 {%0,%1},%2;" : "=f"(lo), "=f"(hi) : "l"(v));
}
__device__ __forceinline__ u64 fma2(u64 a, u64 b, u64 c) {
    u64 d; asm("fma.rn.f32x2 %0,%1,%2,%3;" : "=l"(d) : "l"(a), "l"(b), "l"(c)); return d;
}

__device__ float d_xin[GN * H_];
__device__ int   d_eic[2 * E_];
__device__ float d_ewc[E_];
__device__ float d_Wg[3 * 4096];
__device__ float d_bg[3 * 64];
__device__ float d_Wa[3 * 4096];
__device__ float d_asw[3 * 64];
__device__ float d_adw[3 * 64];
__device__ float d_ba[3 * 64];
__device__ float d_Wt[3 * 20480];
__device__ float d_bt[3 * 64];
__device__ float d_lngc[3 * 64];
__device__ float d_lnbc[3 * 64];
__device__ float d_W1c[NH * 256];
__device__ float d_b1c[256];
__device__ float d_W2c[256 * 64];
__device__ float d_b2c[64];

__device__ float  d_h[GN * H_];
__device__ float  d_bufA[GN * H_];
__device__ int    d_csr_ptr[N_ + 1];
__device__ int    d_csr_eid[E2_];
__device__ int    d_csr_dst[E2_];
__device__ float  d_dis[N_];
__device__ float2 d_csr_sg[E2_];      // {src*64 (bits), gnorm}
__device__ int    d_cnt[CHUNK_ * N_];
__device__ float  d_xt0[B_ * N_ * H_ * T_];
__device__ float  d_part[N_ * G_ * 256];

__device__ __forceinline__ float gelu_f(float x) {
    return 0.5f * x * (1.0f + erff(x * 0.70710678118654752f));
}

// ---------------- staging ----------------
__global__ void k_stageA(const int* ei, const float* ew, const float* Wg,
                         const float* bg, const float* Wa, const float* asw,
                         const float* adw, const float* ba, const float* lng,
                         const float* lnb) {
    int i0 = blockIdx.x * 256 + threadIdx.x, st = gridDim.x * 256;
    for (int i = i0; i < 2 * E_; i += st) d_eic[i] = ei[i];
    for (int i = i0; i < E_;    i += st) d_ewc[i] = ew[i];
    for (int i = i0; i < 12288; i += st) { d_Wg[i] = Wg[i]; d_Wa[i] = Wa[i]; }
    for (int i = i0; i < CHUNK_ * N_; i += st) d_cnt[i] = 0;
    for (int i = i0; i < 192;   i += st) {
        d_bg[i] = bg[i]; d_asw[i] = asw[i]; d_adw[i] = adw[i];
        d_ba[i] = ba[i]; d_lngc[i] = lng[i]; d_lnbc[i] = lnb[i];
    }
}
__global__ void k_stageB(const float* Wt, const float* bt, const float* b1,
                         const float* W2, const float* b2) {
    int i0 = blockIdx.x * 256 + threadIdx.x, st = gridDim.x * 256;
    for (int i = i0; i < 61440; i += st) d_Wt[i] = Wt[i];
    for (int i = i0; i < 192;   i += st) d_bt[i] = bt[i];
    for (int i = i0; i < 256;   i += st) d_b1c[i] = b1[i];
    for (int i = i0; i < 16384; i += st) d_W2c[i] = W2[i];
    for (int i = i0; i < 64;    i += st) d_b2c[i] = b2[i];
}

// ---------------- prep trio (parallel) ----------------
__global__ void k_prepA() {
    int t = threadIdx.x;
    const int* dsts = d_eic + E_;
    const int EC = (E_ + CHUNK_ - 1) / CHUNK_;
    int e0 = t * EC, e1 = min(e0 + EC, E_);
    __shared__ int ptr_s[N_ + 1];
    for (int e = e0; e < e1; e++) d_cnt[t * N_ + dsts[e]]++;
    __syncthreads();
    if (t < N_) {
        int run = 0;
        for (int c = 0; c < CHUNK_; c++) {
            int idx = c * N_ + t;
            int v = d_cnt[idx]; d_cnt[idx] = run; run += v;
        }
        ptr_s[t] = run + 1;
    }
    __syncthreads();
    if (t == 0) {
        int p = 0;
        for (int n = 0; n < N_; n++) { int v = ptr_s[n]; ptr_s[n] = p; p += v; }
        ptr_s[N_] = p;
    }
    __syncthreads();
    if (t <= N_) d_csr_ptr[t] = ptr_s[t];
    for (int e = e0; e < e1; e++) {
        int d = dsts[e];
        int pos = ptr_s[d] + d_cnt[t * N_ + d]++;
        d_csr_eid[pos] = e; d_csr_dst[pos] = d;
    }
    __syncthreads();
    if (t < N_) {
        int pos = ptr_s[t + 1] - 1;
        d_csr_eid[pos] = E_ + t; d_csr_dst[pos] = t;
    }
}

__global__ void k_prepB() {
    int n = blockIdx.x * 4 + (threadIdx.x >> 5);
    int lane = threadIdx.x & 31;
    if (n >= N_) return;
    int p0 = d_csr_ptr[n], p1 = d_csr_ptr[n + 1] - 1;
    float s = 0.0f;
    for (int p = p0 + lane; p < p1; p += 32) s += d_ewc[d_csr_eid[p]];
    #pragma unroll
    for (int off = 16; off; off >>= 1) s += __shfl_xor_sync(~0u, s, off);
    if (lane == 0) d_dis[n] = rsqrtf(s + 1.0f);
}

__global__ void k_prepC() {
    int pos = blockIdx.x * 256 + threadIdx.x;
    if (pos >= E2_) return;
    int e = d_csr_eid[pos], d = d_csr_dst[pos];
    float dd = d_dis[d];
    int s; float gn;
    if (e < E_) { s = d_eic[e]; gn = d_dis[s] * d_ewc[e] * dd; }
    else        { s = d;        gn = dd * dd; }
    d_csr_sg[pos] = make_float2(__int_as_float(s * 64), gn);   // pre-scaled
}

// ------- in-block 370x64 @ 64x64 GEMM (512 threads), scalar FFMA -------
__device__ __forceinline__ void gemm_block(const float* __restrict__ in_s,
                                           const float* __restrict__ WsT,
                                           float* __restrict__ out_s, int tid) {
    int c = tid & 63, rb = tid >> 6;
    const float* wc = WsT + c * 68;
    float w[64];
    #pragma unroll
    for (int k = 0; k < 64; k += 4) *(float4*)&w[k] = *(const float4*)&wc[k];
    for (int r = rb; r < 185; r += 8) {
        int r2 = r + 185;
        float a0 = 0.f, a1 = 0.f, a2 = 0.f, a3 = 0.f;
        #pragma unroll
        for (int k = 0; k < 64; k += 4) {
            float4 h0 = *(const float4*)&in_s[r * 64 + k];
            float4 h1 = *(const float4*)&in_s[r2 * 64 + k];
            a0 = fmaf(h0.x, w[k], a0);     a1 = fmaf(h0.y, w[k + 1], a1);
            a0 = fmaf(h0.z, w[k + 2], a0); a1 = fmaf(h0.w, w[k + 3], a1);
            a2 = fmaf(h1.x, w[k], a2);     a3 = fmaf(h1.y, w[k + 1], a3);
            a2 = fmaf(h1.z, w[k + 2], a2); a3 = fmaf(h1.w, w[k + 3], a3);
        }
        out_s[r * 64 + c]  = a0 + a1;
        out_s[r2 * 64 + c] = a2 + a3;
    }
}

// ---------------- K1: GCN layer ----------------
#define GCN_SMEM ((2 * NH + 64 * 68) * 4)
__global__ void k_gcn(const float* __restrict__ hin, const float* __restrict__ Wg,
                      const float* __restrict__ bg, float* __restrict__ gout) {
    extern __shared__ __align__(16) float sm[];
    float* h_s  = sm;
    float* hw_s = sm + NH;
    float* WsT  = sm + 2 * NH;
    int g = blockIdx.x, tid = threadIdx.x;
    const float* hrow = hin + (size_t)g * NH;
    for (int i = tid * 4; i < NH; i += 2048)
        *(float4*)&h_s[i] = *(const float4*)&hrow[i];
    for (int i = tid; i < 4096; i += 512)
        WsT[(i & 63) * 68 + (i >> 6)] = Wg[i];
    __syncthreads();
    gemm_block(h_s, WsT, hw_s, tid);
    __syncthreads();

    int lane = tid & 31, w = tid >> 5;
    float2* scr = (float2*)(h_s + w * 1480);
    float bx = bg[2 * lane], by = bg[2 * lane + 1];
    for (int d = w; d < N_; d += 16) {
        int p0 = d_csr_ptr[d], deg = d_csr_ptr[d + 1] - p0;
        for (int j = lane; j < deg; j += 32) scr[j] = d_csr_sg[p0 + j];
        __syncwarp();
        float2 a0 = {0.f, 0.f}, a1 = {0.f, 0.f}, a2 = {0.f, 0.f}, a3 = {0.f, 0.f};
        int j = 0;
        for (; j + 4 <= deg; j += 4) {
            float2 s0 = scr[j],     s1 = scr[j + 1];
            float2 s2 = scr[j + 2], s3 = scr[j + 3];
            float2 v0 = *(const float2*)&hw_s[__float_as_int(s0.x) + 2 * lane];
            float2 v1 = *(const float2*)&hw_s[__float_as_int(s1.x) + 2 * lane];
            float2 v2 = *(const float2*)&hw_s[__float_as_int(s2.x) + 2 * lane];
            float2 v3 = *(const float2*)&hw_s[__float_as_int(s3.x) + 2 * lane];
            a0.x = fmaf(s0.y, v0.x, a0.x); a0.y = fmaf(s0.y, v0.y, a0.y);
            a1.x = fmaf(s1.y, v1.x, a1.x); a1.y = fmaf(s1.y, v1.y, a1.y);
            a2.x = fmaf(s2.y, v2.x, a2.x); a2.y = fmaf(s2.y, v2.y, a2.y);
            a3.x = fmaf(s3.y, v3.x, a3.x); a3.y = fmaf(s3.y, v3.y, a3.y);
        }
        for (; j < deg; j++) {
            float2 s0 = scr[j];
            float2 v0 = *(const float2*)&hw_s[__float_as_int(s0.x) + 2 * lane];
            a0.x = fmaf(s0.y, v0.x, a0.x); a0.y = fmaf(s0.y, v0.y, a0.y);
        }
        __syncwarp();
        float gx = (a0.x + a1.x) + (a2.x + a3.x) + bx;
        float gy = (a0.y + a1.y) + (a2.y + a3.y) + by;
        *(float2*)&gout[((size_t)g * N_ + d) * 64 + 2 * lane] =
            make_float2(gelu_f(gx), gelu_f(gy));
    }
}

// ---------------- K2: GAT + residual + LN ----------------
#define GAT2_SMEM ((2 * NH + 64 * 68 + N_ * 4) * 4)
__global__ void k_gat2(const float* __restrict__ gin, const float* __restrict__ Wa,
                       const float* __restrict__ attS, const float* __restrict__ attD,
                       const float* __restrict__ ba, const float* __restrict__ lng,
                       const float* __restrict__ lnb, const float* __restrict__ hin,
                       float* __restrict__ hout) {
    extern __shared__ __align__(16) float sm[];
    float* g_s    = sm;
    float* gh_s   = sm + NH;
    float* WsT    = sm + 2 * NH;
    float* asrc_s = sm + 2 * NH + 64 * 68;
    int g = blockIdx.x, tid = threadIdx.x;
    const float* grow = gin + (size_t)g * NH;
    for (int i = tid * 4; i < NH; i += 2048)
        *(float4*)&g_s[i] = *(const float4*)&grow[i];
    for (int i = tid; i < 4096; i += 512)
        WsT[(i & 63) * 68 + (i >> 6)] = Wa[i];
    __syncthreads();
    gemm_block(g_s, WsT, gh_s, tid);
    __syncthreads();

    int lane = tid & 31, w = tid >> 5, hh = lane >> 3;
    float wsl = attS[lane], wsl2 = attS[lane + 32];
    float wdl = attD[lane], wdl2 = attD[lane + 32];
    for (int n = w; n < N_; n += 16) {
        float r1 = gh_s[n * 64 + lane] * wsl;
        float r2 = gh_s[n * 64 + 32 + lane] * wsl2;
        #pragma unroll
        for (int off = 8; off; off >>= 1) {
            r1 += __shfl_xor_sync(~0u, r1, off, 16);
            r2 += __shfl_xor_sync(~0u, r2, off, 16);
        }
        if (lane == 0)       { asrc_s[n * 4 + 0] = r1; asrc_s[n * 4 + 2] = r2; }
        else if (lane == 16) { asrc_s[n * 4 + 1] = r1; asrc_s[n * 4 + 3] = r2; }
    }
    __syncthreads();

    float* scrA = g_s + w * 1480;
    int*   scrS = (int*)(scrA + DCAP * 4);
    float bx  = ba[2 * lane],  by  = ba[2 * lane + 1];
    float gsx = lng[2 * lane], gsy = lng[2 * lane + 1];
    float gbx = lnb[2 * lane], gby = lnb[2 * lane + 1];

    for (int d = w; d < N_; d += 16) {
        float r1 = gh_s[d * 64 + lane] * wdl;
        float r2 = gh_s[d * 64 + 32 + lane] * wdl2;
        #pragma unroll
        for (int off = 8; off; off >>= 1) {
            r1 += __shfl_xor_sync(~0u, r1, off, 16);
            r2 += __shfl_xor_sync(~0u, r2, off, 16);
        }
        float h0 = __shfl_sync(~0u, r1, 0),  h1 = __shfl_sync(~0u, r1, 16);
        float h2 = __shfl_sync(~0u, r2, 0),  h3 = __shfl_sync(~0u, r2, 16);

        int p0 = d_csr_ptr[d], deg = d_csr_ptr[d + 1] - p0;
        float2 acc = {0.f, 0.f};
        float invh;
        if (deg <= DCAP) {
            float m0 = -1e30f, m1 = -1e30f, m2 = -1e30f, m3 = -1e30f;
            for (int j = lane; j < deg; j += 32) {
                float2 sgv = d_csr_sg[p0 + j];
                int soff = __float_as_int(sgv.x);
                float4 av = *(const float4*)&asrc_s[soff >> 4];
                float a0 = av.x + h0, a1 = av.y + h1, a2 = av.z + h2, a3 = av.w + h3;
                a0 = fmaxf(a0, 0.2f * a0); a1 = fmaxf(a1, 0.2f * a1);
                a2 = fmaxf(a2, 0.2f * a2); a3 = fmaxf(a3, 0.2f * a3);
                scrA[j * 4 + 0] = a0; scrA[j * 4 + 1] = a1;
                scrA[j * 4 + 2] = a2; scrA[j * 4 + 3] = a3;
                scrS[j] = soff;
                m0 = fmaxf(m0, a0); m1 = fmaxf(m1, a1);
                m2 = fmaxf(m2, a2); m3 = fmaxf(m3, a3);
            }
            #pragma unroll
            for (int off = 16; off; off >>= 1) {
                m0 = fmaxf(m0, __shfl_xor_sync(~0u, m0, off));
                m1 = fmaxf(m1, __shfl_xor_sync(~0u, m1, off));
                m2 = fmaxf(m2, __shfl_xor_sync(~0u, m2, off));
                m3 = fmaxf(m3, __shfl_xor_sync(~0u, m3, off));
            }
            __syncwarp();
            float d0 = 0.f, d1 = 0.f, d2 = 0.f, d3 = 0.f;
            for (int j = lane; j < deg; j += 32) {
                float e0 = __expf(scrA[j * 4 + 0] - m0);
                float e1 = __expf(scrA[j * 4 + 1] - m1);
                float e2 = __expf(scrA[j * 4 + 2] - m2);
                float e3 = __expf(scrA[j * 4 + 3] - m3);
                scrA[j * 4 + 0] = e0; scrA[j * 4 + 1] = e1;
                scrA[j * 4 + 2] = e2; scrA[j * 4 + 3] = e3;
                d0 += e0; d1 += e1; d2 += e2; d3 += e3;
            }
            #pragma unroll
            for (int off = 16; off; off >>= 1) {
                d0 += __shfl_xor_sync(~0u, d0, off);
                d1 += __shfl_xor_sync(~0u, d1, off);
                d2 += __shfl_xor_sync(~0u, d2, off);
                d3 += __shfl_xor_sync(~0u, d3, off);
            }
            invh = 1.0f / ((hh == 0) ? d0 : (hh == 1) ? d1 : (hh == 2) ? d2 : d3);
            __syncwarp();
            float2 acc2 = {0.f, 0.f};
            int j = 0;
            for (; j + 2 <= deg; j += 2) {
                float al0 = scrA[j * 4 + hh], al1 = scrA[(j + 1) * 4 + hh];
                float2 v0 = *(const float2*)&gh_s[scrS[j] + 2 * lane];
                float2 v1 = *(const float2*)&gh_s[scrS[j + 1] + 2 * lane];
                acc.x  = fmaf(al0, v0.x, acc.x);  acc.y  = fmaf(al0, v0.y, acc.y);
                acc2.x = fmaf(al1, v1.x, acc2.x); acc2.y = fmaf(al1, v1.y, acc2.y);
            }
            if (j < deg) {
                float al = scrA[j * 4 + hh];
                float2 v = *(const float2*)&gh_s[scrS[j] + 2 * lane];
                acc.x = fmaf(al, v.x, acc.x); acc.y = fmaf(al, v.y, acc.y);
            }
            acc.x += acc2.x; acc.y += acc2.y;
        } else {
            float adh = (hh == 0) ? h0 : (hh == 1) ? h1 : (hh == 2) ? h2 : h3;
            float m = -1e30f;
            for (int p = p0; p < p0 + deg; p++) {
                float a = asrc_s[(__float_as_int(d_csr_sg[p].x) >> 4) + hh] + adh;
                a = fmaxf(a, 0.2f * a);
                m = fmaxf(m, a);
            }
            float den = 0.f;
            for (int p = p0; p < p0 + deg; p++) {
                int soff = __float_as_int(d_csr_sg[p].x);
                float a = asrc_s[(soff >> 4) + hh] + adh;
                a = fmaxf(a, 0.2f * a);
                float e = __expf(a - m);
                den += e;
                float2 v = *(const float2*)&gh_s[soff + 2 * lane];
                acc.x = fmaf(e, v.x, acc.x); acc.y = fmaf(e, v.y, acc.y);
            }
            invh = 1.0f / den;
        }
        float rx = acc.x * invh + bx + hin[((size_t)g * N_ + d) * 64 + 2 * lane];
        float ry = acc.y * invh + by + hin[((size_t)g * N_ + d) * 64 + 2 * lane + 1];
        float s1 = rx + ry, s2 = rx * rx + ry * ry;
        #pragma unroll
        for (int off = 16; off; off >>= 1) {
            s1 += __shfl_xor_sync(~0u, s1, off);
            s2 += __shfl_xor_sync(~0u, s2, off);
        }
        float mu = s1 * (1.0f / 64.0f);
        float var = fmaxf(s2 * (1.0f / 64.0f) - mu * mu, 0.0f);
        float inv = rsqrtf(var + 1e-5f);
        *(float2*)&hout[((size_t)g * N_ + d) * 64 + 2 * lane] =
            make_float2((rx - mu) * inv * gsx + gbx, (ry - mu) * inv * gsy + gby);
    }
}

// ------- fused 3-layer temporal conv, splatted f32x2, 5 bn x 640 threads -------
#define TC5_BN 5
#define TC5_THREADS 640
#define TC5_XS 2304
#define TC5_SMEM ((10240 + TC5_BN * TC5_XS) * 8)

__global__ void k_tconv3(const float* __restrict__ in_h, float* __restrict__ out,
                         const float* __restrict__ Wt_all, const float* __restrict__ bt_all) {
    extern __shared__ __align__(16) u64 smu[];
    u64* wsu = smu;
    u64* xs  = smu + 10240;
    int tid = threadIdx.x;
    int bn0 = blockIdx.x * TC5_BN;

    for (int i = tid; i < TC5_BN * TC5_XS; i += TC5_THREADS) xs[i] = 0ULL;
    __syncthreads();
    for (int idx = tid; idx < TC5_BN * 2048; idx += TC5_THREADS) {
        int bnL = idx >> 11, r = idx & 2047, bn = bn0 + bnL;
        int tt = r >> 6, ch = r & 63;
        int b = bn / N_, n = bn % N_;
        float v = in_h[(((size_t)(b * 32 + tt) * N_) + n) * 64 + ch];
        xs[bnL * TC5_XS + ch * 36 + 2 + tt] = pk2(v, v);
    }

    int bnL = tid / 128, t7 = tid % 128;
    int op = t7 & 31, t0 = (t7 >> 5) * 8;
    int ch0 = 2 * op, ch1 = 2 * op + 1;
    u64* xb = xs + bnL * TC5_XS;

    for (int p = 0; p < 3; p++) {
        __syncthreads();
        const float* W = Wt_all + p * 20480;
        for (int i = tid; i < 10240; i += TC5_THREADS) {
            int opx = i & 31, r = i >> 5;
            wsu[r * 32 + opx] = pk2(W[(2 * opx) * 320 + r], W[(2 * opx + 1) * 320 + r]);
        }
        __syncthreads();

        u64 bp = pk2(bt_all[p * 64 + ch0], bt_all[p * 64 + ch1]);
        u64 acc2[8];
        #pragma unroll
        for (int u = 0; u < 8; u++) acc2[u] = bp;

        for (int i = 0; i < 64; i++) {
            const u64* xi = xb + i * 36 + t0;
            u64 win[12];
            #pragma unroll
            for (int j = 0; j < 12; j++) win[j] = xi[j];
            const u64* wr = wsu + (i * 5) * 32 + op;
            u64 w0 = wr[0], w1 = wr[32], w2 = wr[64], w3 = wr[96], w4 = wr[128];
            #pragma unroll
            for (int u = 0; u < 8; u++) {
                u64 a = acc2[u];
                a = fma2(win[u],     w0, a);
                a = fma2(win[u + 1], w1, a);
                a = fma2(win[u + 2], w2, a);
                a = fma2(win[u + 3], w3, a);
                a = fma2(win[u + 4], w4, a);
                acc2[u] = a;
            }
        }
        __syncthreads();

        if (p < 2) {
            #pragma unroll
            for (int u = 0; u < 8; u++) {
                float a, b;
                upk2(acc2[u], a, b);
                int t = t0 + u;
                float x0, x1, dum;
                upk2(xb[ch0 * 36 + 2 + t], x0, dum);
                upk2(xb[ch1 * 36 + 2 + t], x1, dum);
                float n0 = gelu_f(a) + x0;
                float n1 = gelu_f(b) + x1;
                xb[ch0 * 36 + 2 + t] = pk2(n0, n0);
                xb[ch1 * 36 + 2 + t] = pk2(n1, n1);
            }
        } else {
            int bn = bn0 + bnL;
            float* ob = out + (size_t)bn * 2048;
            #pragma unroll
            for (int u = 0; u < 8; u++) {
                float a, b;
                upk2(acc2[u], a, b);
                int t = t0 + u;
                float x0, x1, dum;
                upk2(xb[ch0 * 36 + 2 + t], x0, dum);
                upk2(xb[ch1 * 36 + 2 + t], x1, dum);
                ob[ch0 * 32 + t] = gelu_f(a) + x0;
                ob[ch1 * 32 + t] = gelu_f(b) + x1;
            }
        }
    }
}

// ---------------- MLP1 split-K (scalar) ----------------
#define ZS_STRIDE 65
#define MLP1_SMEM ((G_ * ZS_STRIDE + 64 * 256) * 4)
__global__ void k_mlp1(const float* __restrict__ xt, const float* __restrict__ W1) {
    extern __shared__ __align__(16) float sm[];
    float* zs  = sm;
    float* w1s = sm + G_ * ZS_STRIDE;
    int n = blockIdx.x, tid = threadIdx.x;
    for (int i = tid; i < 8192; i += 256) {
        int b = i >> 11, c = (i >> 5) & 63, t = i & 31;
        zs[(b * 32 + t) * ZS_STRIDE + c] = xt[(((size_t)(b * N_ + n)) * 64 + c) * 32 + t];
    }
    for (int i = tid; i < 16384; i += 256)
        w1s[i] = W1[(size_t)n * 16384 + i];
    __syncthreads();
    int ow = tid & 31, gw = tid >> 5, o0 = ow * 8;
    float* pb = d_part + (size_t)n * (G_ * 256);
    for (int pass = 0; pass < 4; pass++) {
        int g0 = pass * 32 + gw * 4;
        float acc[4][8] = {};
        #pragma unroll 4
        for (int k = 0; k < 64; k++) {
            float4 wa = *(const float4*)&w1s[k * 256 + o0];
            float4 wb = *(const float4*)&w1s[k * 256 + o0 + 4];
            float wv[8] = {wa.x, wa.y, wa.z, wa.w, wb.x, wb.y, wb.z, wb.w};
            float z[4];
            #pragma unroll
            for (int j = 0; j < 4; j++) z[j] = zs[(g0 + j) * ZS_STRIDE + k];
            #pragma unroll
            for (int j = 0; j < 4; j++)
                #pragma unroll
                for (int q = 0; q < 8; q++)
                    acc[j][q] = fmaf(z[j], wv[q], acc[j][q]);
        }
        #pragma unroll
        for (int j = 0; j < 4; j++) {
            *(float4*)&pb[(g0 + j) * 256 + o0]     = make_float4(acc[j][0], acc[j][1], acc[j][2], acc[j][3]);
            *(float4*)&pb[(g0 + j) * 256 + o0 + 4] = make_float4(acc[j][4], acc[j][5], acc[j][6], acc[j][7]);
        }
    }
}

__global__ void k_redmlp2(const float* __restrict__ b1, const float* __restrict__ W2,
                          const float* __restrict__ b2, float* __restrict__ out) {
    __shared__ float hid[256];
    int g = blockIdx.x, o = threadIdx.x;
    float a0 = 0.f, a1 = 0.f;
    size_t base = (size_t)g * 256 + o;
    int nb = 0;
    for (; nb + 2 <= N_; nb += 2) {
        a0 += d_part[(size_t)nb * (G_ * 256) + base];
        a1 += d_part[(size_t)(nb + 1) * (G_ * 256) + base];
    }
    for (; nb < N_; nb++) a0 += d_part[(size_t)nb * (G_ * 256) + base];
    hid[o] = gelu_f(a0 + a1 + b1[o]);
    __syncthreads();
    if (o < 64) {
        float acc = b2[o];
        #pragma unroll 8
        for (int k = 0; k < 256; k++) acc = fmaf(hid[k], W2[k * 64 + o], acc);
        out[(size_t)g * 64 + o] = acc;
    }
}

extern "C" void kernel_launch(void* const* d_in, const int* in_sizes, int n_in,
                              void* d_out, int out_size) {
    float* out = (float*)d_out;
    static cudaStream_t s2 = nullptr;
    static cudaEvent_t evFork = nullptr, evX = nullptr, evJoin = nullptr;
    if (s2 == nullptr) {
        cudaStreamCreateWithFlags(&s2, cudaStreamNonBlocking);
        cudaEventCreateWithFlags(&evFork, cudaEventDisableTiming);
        cudaEventCreateWithFlags(&evX,    cudaEventDisableTiming);
        cudaEventCreateWithFlags(&evJoin, cudaEventDisableTiming);
        cudaFuncSetAttribute(k_gcn,    cudaFuncAttributeMaxDynamicSharedMemorySize, GCN_SMEM);
        cudaFuncSetAttribute(k_gat2,   cudaFuncAttributeMaxDynamicSharedMemorySize, GAT2_SMEM);
        cudaFuncSetAttribute(k_tconv3, cudaFuncAttributeMaxDynamicSharedMemorySize, TC5_SMEM);
        cudaFuncSetAttribute(k_mlp1,   cudaFuncAttributeMaxDynamicSharedMemorySize, MLP1_SMEM);
    }

    cudaEventRecord(evFork, 0);
    cudaStreamWaitEvent(s2, evFork, 0);
    cudaMemcpyToSymbolAsync(d_xin, d_in[0], (size_t)GN * H_ * 4, 0, cudaMemcpyDeviceToDevice, s2);
    cudaEventRecord(evX, s2);
    cudaMemcpyToSymbolAsync(d_W1c, d_in[13], (size_t)NH * 256 * 4, 0, cudaMemcpyDeviceToDevice, s2);
    k_stageB<<<48, 256, 0, s2>>>((const float*)d_in[9], (const float*)d_in[10],
                                 (const float*)d_in[14], (const float*)d_in[15],
                                 (const float*)d_in[16]);
    cudaEventRecord(evJoin, s2);

    k_stageA<<<64, 256>>>((const int*)d_in[1], (const float*)d_in[2],
                          (const float*)d_in[3], (const float*)d_in[4],
                          (const float*)d_in[5], (const float*)d_in[6],
                          (const float*)d_in[7], (const float*)d_in[8],
                          (const float*)d_in[11], (const float*)d_in[12]);
    k_prepA<<<1, CHUNK_>>>();
    k_prepB<<<(N_ + 3) / 4, 128>>>();
    k_prepC<<<(E2_ + 255) / 256, 256>>>();
    cudaStreamWaitEvent(0, evX, 0);

    float *xin, *Wg, *bg, *Wa, *asw, *adw, *ba, *Wt, *bt, *lng, *lnb, *W1, *b1, *W2, *b2;
    float *hbuf, *bufA, *xt0;
    cudaGetSymbolAddress((void**)&xin,  d_xin);
    cudaGetSymbolAddress((void**)&Wg,   d_Wg);
    cudaGetSymbolAddress((void**)&bg,   d_bg);
    cudaGetSymbolAddress((void**)&Wa,   d_Wa);
    cudaGetSymbolAddress((void**)&asw,  d_asw);
    cudaGetSymbolAddress((void**)&adw,  d_adw);
    cudaGetSymbolAddress((void**)&ba,   d_ba);
    cudaGetSymbolAddress((void**)&Wt,   d_Wt);
    cudaGetSymbolAddress((void**)&bt,   d_bt);
    cudaGetSymbolAddress((void**)&lng,  d_lngc);
    cudaGetSymbolAddress((void**)&lnb,  d_lnbc);
    cudaGetSymbolAddress((void**)&W1,   d_W1c);
    cudaGetSymbolAddress((void**)&b1,   d_b1c);
    cudaGetSymbolAddress((void**)&W2,   d_W2c);
    cudaGetSymbolAddress((void**)&b2,   d_b2c);
    cudaGetSymbolAddress((void**)&hbuf, d_h);
    cudaGetSymbolAddress((void**)&bufA, d_bufA);
    cudaGetSymbolAddress((void**)&xt0,  d_xt0);

    const float* hin = xin;
    for (int l = 0; l < 3; l++) {
        k_gcn<<<G_, 512, GCN_SMEM>>>(hin, Wg + l * 4096, bg + l * 64, bufA);
        k_gat2<<<G_, 512, GAT2_SMEM>>>(bufA, Wa + l * 4096, asw + l * 64, adw + l * 64,
                                       ba + l * 64, lng + l * 64, lnb + l * 64, hin, hbuf);
        hin = hbuf;
    }

    cudaStreamWaitEvent(0, evJoin, 0);
    k_tconv3<<<(B_ * N_) / TC5_BN, TC5_THREADS, TC5_SMEM>>>(hbuf, xt0, Wt, bt);

    k_mlp1<<<N_, 256, MLP1_SMEM>>>(xt0, W1);
    k_redmlp2<<<G_, 256>>>(b1, W2, b2, out);
}

// round 14
// speedup vs baseline: 1.0934x; 1.0257x over previous
#include <cuda_runtime.h>
#include <math.h>

#define B_   4
#define T_   32
#define N_   370
#define E_   11840
#define E2_  (E_ + N_)
#define G_   128
#define H_   64
#define GN   (G_ * N_)
#define NH   (N_ * H_)
#define CHUNK_ 512
#define DCAP 192
#define LTH  768
#define NWARP (LTH / 32)
#define WSCR 986
#define GCH 480

typedef unsigned long long u64;
__device__ __forceinline__ u64 pk2(float lo, float hi) {
    u64 r; asm("mov.b64 %0,{%1,%2};" : "=l"(r) : "f"(lo), "f"(hi)); return r;
}
__device__ __forceinline__ void upk2(u64 v, float& lo, float& hi) {
    asm("mov.b64 {%0,%1},%2;" : "=f"(lo), "=f"(hi) : "l"(v));
}
__device__ __forceinline__ u64 fma2(u64 a, u64 b, u64 c) {
    u64 d; asm("fma.rn.f32x2 %0,%1,%2,%3;" : "=l"(d) : "l"(a), "l"(b), "l"(c)); return d;
}

__device__ float d_xin[GN * H_];
__device__ int   d_eic[2 * E_];
__device__ float d_ewc[E_];
__device__ float d_Wg[3 * 4096];
__device__ float d_bg[3 * 64];
__device__ float d_Wa[3 * 4096];
__device__ float d_asw[3 * 64];
__device__ float d_adw[3 * 64];
__device__ float d_ba[3 * 64];
__device__ float d_Wt[3 * 20480];
__device__ float d_bt[3 * 64];
__device__ float d_lngc[3 * 64];
__device__ float d_lnbc[3 * 64];
__device__ float d_W1c[NH * 256];
__device__ float d_b1c[256];
__device__ float d_W2c[256 * 64];
__device__ float d_b2c[64];

__device__ float  d_h[GN * H_];
__device__ float  d_bufA[GN * H_];
__device__ int    d_csr_ptr[N_ + 1];
__device__ int    d_csr_eid[E2_];
__device__ int    d_csr_dst[E2_];
__device__ float  d_dis[N_];
__device__ float2 d_csr_sg[E2_];      // {src*64 (bits), gnorm}
__device__ int    d_cnt[CHUNK_ * N_];
__device__ float  d_xt0[B_ * N_ * H_ * T_];
__device__ float  d_part[N_ * G_ * 256];

__device__ __forceinline__ float gelu_f(float x) {
    return 0.5f * x * (1.0f + erff(x * 0.70710678118654752f));
}

// ---------------- staging ----------------
__global__ void k_stageA(const int* ei, const float* ew, const float* Wg,
                         const float* bg, const float* Wa, const float* asw,
                         const float* adw, const float* ba, const float* lng,
                         const float* lnb) {
    int i0 = blockIdx.x * 256 + threadIdx.x, st = gridDim.x * 256;
    for (int i = i0; i < 2 * E_; i += st) d_eic[i] = ei[i];
    for (int i = i0; i < E_;    i += st) d_ewc[i] = ew[i];
    for (int i = i0; i < 12288; i += st) { d_Wg[i] = Wg[i]; d_Wa[i] = Wa[i]; }
    for (int i = i0; i < CHUNK_ * N_; i += st) d_cnt[i] = 0;
    for (int i = i0; i < 192;   i += st) {
        d_bg[i] = bg[i]; d_asw[i] = asw[i]; d_adw[i] = adw[i];
        d_ba[i] = ba[i]; d_lngc[i] = lng[i]; d_lnbc[i] = lnb[i];
    }
}
__global__ void k_stageB(const float* Wt, const float* bt, const float* b1,
                         const float* W2, const float* b2) {
    int i0 = blockIdx.x * 256 + threadIdx.x, st = gridDim.x * 256;
    for (int i = i0; i < 61440; i += st) d_Wt[i] = Wt[i];
    for (int i = i0; i < 192;   i += st) d_bt[i] = bt[i];
    for (int i = i0; i < 256;   i += st) d_b1c[i] = b1[i];
    for (int i = i0; i < 16384; i += st) d_W2c[i] = W2[i];
    for (int i = i0; i < 64;    i += st) d_b2c[i] = b2[i];
}

// ---------------- prep trio ----------------
__global__ void k_prepA() {
    int t = threadIdx.x;
    const int* dsts = d_eic + E_;
    const int EC = (E_ + CHUNK_ - 1) / CHUNK_;
    int e0 = t * EC, e1 = min(e0 + EC, E_);
    __shared__ int ptr_s[N_ + 1];
    for (int e = e0; e < e1; e++) d_cnt[t * N_ + dsts[e]]++;
    __syncthreads();
    if (t < N_) {
        int run = 0;
        for (int c = 0; c < CHUNK_; c++) {
            int idx = c * N_ + t;
            int v = d_cnt[idx]; d_cnt[idx] = run; run += v;
        }
        ptr_s[t] = run + 1;
    }
    __syncthreads();
    if (t == 0) {
        int p = 0;
        for (int n = 0; n < N_; n++) { int v = ptr_s[n]; ptr_s[n] = p; p += v; }
        ptr_s[N_] = p;
    }
    __syncthreads();
    if (t <= N_) d_csr_ptr[t] = ptr_s[t];
    for (int e = e0; e < e1; e++) {
        int d = dsts[e];
        int pos = ptr_s[d] + d_cnt[t * N_ + d]++;
        d_csr_eid[pos] = e; d_csr_dst[pos] = d;
    }
    __syncthreads();
    if (t < N_) {
        int pos = ptr_s[t + 1] - 1;
        d_csr_eid[pos] = E_ + t; d_csr_dst[pos] = t;
    }
}

__global__ void k_prepB() {
    int n = blockIdx.x * 4 + (threadIdx.x >> 5);
    int lane = threadIdx.x & 31;
    if (n >= N_) return;
    int p0 = d_csr_ptr[n], p1 = d_csr_ptr[n + 1] - 1;
    float s = 0.0f;
    for (int p = p0 + lane; p < p1; p += 32) s += d_ewc[d_csr_eid[p]];
    #pragma unroll
    for (int off = 16; off; off >>= 1) s += __shfl_xor_sync(~0u, s, off);
    if (lane == 0) d_dis[n] = rsqrtf(s + 1.0f);
}

__global__ void k_prepC() {
    int pos = blockIdx.x * 256 + threadIdx.x;
    if (pos >= E2_) return;
    int e = d_csr_eid[pos], d = d_csr_dst[pos];
    float dd = d_dis[d];
    int s; float gn;
    if (e < E_) { s = d_eic[e]; gn = d_dis[s] * d_ewc[e] * dd; }
    else        { s = d;        gn = dd * dd; }
    d_csr_sg[pos] = make_float2(__int_as_float(s * 64), gn);
}

// ------- in-block GEMM (LTH threads), two half-K passes, w[32] in regs -------
__device__ __forceinline__ void gemm_block(const float* __restrict__ in_s,
                                           const float* __restrict__ WsT,
                                           float* __restrict__ out_s, int tid) {
    int c = tid & 63, rb = tid >> 6;                 // rb in [0,12)
    const float* wc = WsT + c * 68;
    #pragma unroll
    for (int half = 0; half < 2; half++) {
        float w[32];
        #pragma unroll
        for (int k = 0; k < 32; k += 4)
            *(float4*)&w[k] = *(const float4*)&wc[half * 32 + k];
        const float* inh = in_s + half * 32;
        for (int r = rb; r < 185; r += 12) {
            int r2 = r + 185;
            float a0 = 0.f, a1 = 0.f, a2 = 0.f, a3 = 0.f;
            #pragma unroll
            for (int k = 0; k < 32; k += 4) {
                float4 h0 = *(const float4*)&inh[r * 64 + k];
                float4 h1 = *(const float4*)&inh[r2 * 64 + k];
                a0 = fmaf(h0.x, w[k], a0);     a1 = fmaf(h0.y, w[k + 1], a1);
                a0 = fmaf(h0.z, w[k + 2], a0); a1 = fmaf(h0.w, w[k + 3], a1);
                a2 = fmaf(h1.x, w[k], a2);     a3 = fmaf(h1.y, w[k + 1], a3);
                a2 = fmaf(h1.z, w[k + 2], a2); a3 = fmaf(h1.w, w[k + 3], a3);
            }
            float p01 = a0 + a1, p23 = a2 + a3;
            if (half == 0) {
                out_s[r * 64 + c]  = p01;
                out_s[r2 * 64 + c] = p23;
            } else {
                out_s[r * 64 + c]  += p01;
                out_s[r2 * 64 + c] += p23;
            }
        }
    }
}

// ---------------- K1: GCN layer (768 threads) ----------------
#define GCN_SMEM ((2 * NH + 64 * 68) * 4)
__global__ void __launch_bounds__(LTH)
k_gcn(const float* __restrict__ hin, const float* __restrict__ Wg,
      const float* __restrict__ bg, float* __restrict__ gout) {
    extern __shared__ __align__(16) float sm[];
    float* h_s  = sm;
    float* hw_s = sm + NH;
    float* WsT  = sm + 2 * NH;
    int g = blockIdx.x, tid = threadIdx.x;
    const float* hrow = hin + (size_t)g * NH;
    for (int i = tid * 4; i < NH; i += LTH * 4)
        *(float4*)&h_s[i] = *(const float4*)&hrow[i];
    for (int i = tid; i < 4096; i += LTH)
        WsT[(i & 63) * 68 + (i >> 6)] = Wg[i];
    __syncthreads();
    gemm_block(h_s, WsT, hw_s, tid);
    __syncthreads();

    int lane = tid & 31, w = tid >> 5;
    float2* scr = (float2*)(h_s + w * WSCR);
    float bx = bg[2 * lane], by = bg[2 * lane + 1];
    for (int d = w; d < N_; d += NWARP) {
        int p0 = d_csr_ptr[d], deg = d_csr_ptr[d + 1] - p0;
        float2 a0 = {0.f, 0.f}, a1 = {0.f, 0.f}, a2 = {0.f, 0.f}, a3 = {0.f, 0.f};
        for (int base = 0; base < deg; base += GCH) {
            int m = min(GCH, deg - base);
            for (int j = lane; j < m; j += 32) scr[j] = d_csr_sg[p0 + base + j];
            __syncwarp();
            int j = 0;
            for (; j + 4 <= m; j += 4) {
                float2 s0 = scr[j],     s1 = scr[j + 1];
                float2 s2 = scr[j + 2], s3 = scr[j + 3];
                float2 v0 = *(const float2*)&hw_s[__float_as_int(s0.x) + 2 * lane];
                float2 v1 = *(const float2*)&hw_s[__float_as_int(s1.x) + 2 * lane];
                float2 v2 = *(const float2*)&hw_s[__float_as_int(s2.x) + 2 * lane];
                float2 v3 = *(const float2*)&hw_s[__float_as_int(s3.x) + 2 * lane];
                a0.x = fmaf(s0.y, v0.x, a0.x); a0.y = fmaf(s0.y, v0.y, a0.y);
                a1.x = fmaf(s1.y, v1.x, a1.x); a1.y = fmaf(s1.y, v1.y, a1.y);
                a2.x = fmaf(s2.y, v2.x, a2.x); a2.y = fmaf(s2.y, v2.y, a2.y);
                a3.x = fmaf(s3.y, v3.x, a3.x); a3.y = fmaf(s3.y, v3.y, a3.y);
            }
            for (; j < m; j++) {
                float2 s0 = scr[j];
                float2 v0 = *(const float2*)&hw_s[__float_as_int(s0.x) + 2 * lane];
                a0.x = fmaf(s0.y, v0.x, a0.x); a0.y = fmaf(s0.y, v0.y, a0.y);
            }
            __syncwarp();
        }
        float gx = (a0.x + a1.x) + (a2.x + a3.x) + bx;
        float gy = (a0.y + a1.y) + (a2.y + a3.y) + by;
        *(float2*)&gout[((size_t)g * N_ + d) * 64 + 2 * lane] =
            make_float2(gelu_f(gx), gelu_f(gy));
    }
}

// ---------------- K2: GAT + residual + LN (768 threads) ----------------
#define GAT2_SMEM ((2 * NH + 64 * 68 + N_ * 4) * 4)
__global__ void __launch_bounds__(LTH)
k_gat2(const float* __restrict__ gin, const float* __restrict__ Wa,
       const float* __restrict__ attS, const float* __restrict__ attD,
       const float* __restrict__ ba, const float* __restrict__ lng,
       const float* __restrict__ lnb, const float* __restrict__ hin,
       float* __restrict__ hout) {
    extern __shared__ __align__(16) float sm[];
    float* g_s    = sm;
    float* gh_s   = sm + NH;
    float* WsT    = sm + 2 * NH;
    float* asrc_s = sm + 2 * NH + 64 * 68;
    int g = blockIdx.x, tid = threadIdx.x;
    const float* grow = gin + (size_t)g * NH;
    for (int i = tid * 4; i < NH; i += LTH * 4)
        *(float4*)&g_s[i] = *(const float4*)&grow[i];
    for (int i = tid; i < 4096; i += LTH)
        WsT[(i & 63) * 68 + (i >> 6)] = Wa[i];
    __syncthreads();
    gemm_block(g_s, WsT, gh_s, tid);
    __syncthreads();

    int lane = tid & 31, w = tid >> 5, hh = lane >> 3;
    float wsl = attS[lane], wsl2 = attS[lane + 32];
    float wdl = attD[lane], wdl2 = attD[lane + 32];
    for (int n = w; n < N_; n += NWARP) {
        float r1 = gh_s[n * 64 + lane] * wsl;
        float r2 = gh_s[n * 64 + 32 + lane] * wsl2;
        #pragma unroll
        for (int off = 8; off; off >>= 1) {
            r1 += __shfl_xor_sync(~0u, r1, off, 16);
            r2 += __shfl_xor_sync(~0u, r2, off, 16);
        }
        if (lane == 0)       { asrc_s[n * 4 + 0] = r1; asrc_s[n * 4 + 2] = r2; }
        else if (lane == 16) { asrc_s[n * 4 + 1] = r1; asrc_s[n * 4 + 3] = r2; }
    }
    __syncthreads();

    float* scrA = g_s + w * WSCR;
    int*   scrS = (int*)(scrA + DCAP * 4);
    float bx  = ba[2 * lane],  by  = ba[2 * lane + 1];
    float gsx = lng[2 * lane], gsy = lng[2 * lane + 1];
    float gbx = lnb[2 * lane], gby = lnb[2 * lane + 1];

    for (int d = w; d < N_; d += NWARP) {
        float r1 = gh_s[d * 64 + lane] * wdl;
        float r2 = gh_s[d * 64 + 32 + lane] * wdl2;
        #pragma unroll
        for (int off = 8; off; off >>= 1) {
            r1 += __shfl_xor_sync(~0u, r1, off, 16);
            r2 += __shfl_xor_sync(~0u, r2, off, 16);
        }
        float h0 = __shfl_sync(~0u, r1, 0),  h1 = __shfl_sync(~0u, r1, 16);
        float h2 = __shfl_sync(~0u, r2, 0),  h3 = __shfl_sync(~0u, r2, 16);

        int p0 = d_csr_ptr[d], deg = d_csr_ptr[d + 1] - p0;
        float2 acc = {0.f, 0.f};
        float invh;
        if (deg <= DCAP) {
            float m0 = -1e30f, m1 = -1e30f, m2 = -1e30f, m3 = -1e30f;
            for (int j = lane; j < deg; j += 32) {
                float2 sgv = d_csr_sg[p0 + j];
                int soff = __float_as_int(sgv.x);
                float4 av = *(const float4*)&asrc_s[soff >> 4];
                float a0 = av.x + h0, a1 = av.y + h1, a2 = av.z + h2, a3 = av.w + h3;
                a0 = fmaxf(a0, 0.2f * a0); a1 = fmaxf(a1, 0.2f * a1);
                a2 = fmaxf(a2, 0.2f * a2); a3 = fmaxf(a3, 0.2f * a3);
                scrA[j * 4 + 0] = a0; scrA[j * 4 + 1] = a1;
                scrA[j * 4 + 2] = a2; scrA[j * 4 + 3] = a3;
                scrS[j] = soff;
                m0 = fmaxf(m0, a0); m1 = fmaxf(m1, a1);
                m2 = fmaxf(m2, a2); m3 = fmaxf(m3, a3);
            }
            #pragma unroll
            for (int off = 16; off; off >>= 1) {
                m0 = fmaxf(m0, __shfl_xor_sync(~0u, m0, off));
                m1 = fmaxf(m1, __shfl_xor_sync(~0u, m1, off));
                m2 = fmaxf(m2, __shfl_xor_sync(~0u, m2, off));
                m3 = fmaxf(m3, __shfl_xor_sync(~0u, m3, off));
            }
            __syncwarp();
            float d0 = 0.f, d1 = 0.f, d2 = 0.f, d3 = 0.f;
            for (int j = lane; j < deg; j += 32) {
                float e0 = __expf(scrA[j * 4 + 0] - m0);
                float e1 = __expf(scrA[j * 4 + 1] - m1);
                float e2 = __expf(scrA[j * 4 + 2] - m2);
                float e3 = __expf(scrA[j * 4 + 3] - m3);
                scrA[j * 4 + 0] = e0; scrA[j * 4 + 1] = e1;
                scrA[j * 4 + 2] = e2; scrA[j * 4 + 3] = e3;
                d0 += e0; d1 += e1; d2 += e2; d3 += e3;
            }
            #pragma unroll
            for (int off = 16; off; off >>= 1) {
                d0 += __shfl_xor_sync(~0u, d0, off);
                d1 += __shfl_xor_sync(~0u, d1, off);
                d2 += __shfl_xor_sync(~0u, d2, off);
                d3 += __shfl_xor_sync(~0u, d3, off);
            }
            invh = 1.0f / ((hh == 0) ? d0 : (hh == 1) ? d1 : (hh == 2) ? d2 : d3);
            __syncwarp();
            float2 acc2 = {0.f, 0.f};
            int j = 0;
            for (; j + 2 <= deg; j += 2) {
                float al0 = scrA[j * 4 + hh], al1 = scrA[(j + 1) * 4 + hh];
                float2 v0 = *(const float2*)&gh_s[scrS[j] + 2 * lane];
                float2 v1 = *(const float2*)&gh_s[scrS[j + 1] + 2 * lane];
                acc.x  = fmaf(al0, v0.x, acc.x);  acc.y  = fmaf(al0, v0.y, acc.y);
                acc2.x = fmaf(al1, v1.x, acc2.x); acc2.y = fmaf(al1, v1.y, acc2.y);
            }
            if (j < deg) {
                float al = scrA[j * 4 + hh];
                float2 v = *(const float2*)&gh_s[scrS[j] + 2 * lane];
                acc.x = fmaf(al, v.x, acc.x); acc.y = fmaf(al, v.y, acc.y);
            }
            acc.x += acc2.x; acc.y += acc2.y;
        } else {
            float adh = (hh == 0) ? h0 : (hh == 1) ? h1 : (hh == 2) ? h2 : h3;
            float m = -1e30f;
            for (int p = p0; p < p0 + deg; p++) {
                float a = asrc_s[(__float_as_int(d_csr_sg[p].x) >> 4) + hh] + adh;
                a = fmaxf(a, 0.2f * a);
                m = fmaxf(m, a);
            }
            float den = 0.f;
            for (int p = p0; p < p0 + deg; p++) {
                int soff = __float_as_int(d_csr_sg[p].x);
                float a = asrc_s[(soff >> 4) + hh] + adh;
                a = fmaxf(a, 0.2f * a);
                float e = __expf(a - m);
                den += e;
                float2 v = *(const float2*)&gh_s[soff + 2 * lane];
                acc.x = fmaf(e, v.x, acc.x); acc.y = fmaf(e, v.y, acc.y);
            }
            invh = 1.0f / den;
        }
        float rx = acc.x * invh + bx + hin[((size_t)g * N_ + d) * 64 + 2 * lane];
        float ry = acc.y * invh + by + hin[((size_t)g * N_ + d) * 64 + 2 * lane + 1];
        float s1 = rx + ry, s2 = rx * rx + ry * ry;
        #pragma unroll
        for (int off = 16; off; off >>= 1) {
            s1 += __shfl_xor_sync(~0u, s1, off);
            s2 += __shfl_xor_sync(~0u, s2, off);
        }
        float mu = s1 * (1.0f / 64.0f);
        float var = fmaxf(s2 * (1.0f / 64.0f) - mu * mu, 0.0f);
        float inv = rsqrtf(var + 1e-5f);
        *(float2*)&hout[((size_t)g * N_ + d) * 64 + 2 * lane] =
            make_float2((rx - mu) * inv * gsx + gbx, (ry - mu) * inv * gsy + gby);
    }
}

// ------- fused 3-layer temporal conv, splatted f32x2, 5 bn x 640 threads -------
#define TC5_BN 5
#define TC5_THREADS 640
#define TC5_XS 2304
#define TC5_SMEM ((10240 + TC5_BN * TC5_XS) * 8)

__global__ void k_tconv3(const float* __restrict__ in_h, float* __restrict__ out,
                         const float* __restrict__ Wt_all, const float* __restrict__ bt_all) {
    extern __shared__ __align__(16) u64 smu[];
    u64* wsu = smu;
    u64* xs  = smu + 10240;
    int tid = threadIdx.x;
    int bn0 = blockIdx.x * TC5_BN;

    for (int i = tid; i < TC5_BN * TC5_XS; i += TC5_THREADS) xs[i] = 0ULL;
    __syncthreads();
    for (int idx = tid; idx < TC5_BN * 2048; idx += TC5_THREADS) {
        int bnL = idx >> 11, r = idx & 2047, bn = bn0 + bnL;
        int tt = r >> 6, ch = r & 63;
        int b = bn / N_, n = bn % N_;
        float v = in_h[(((size_t)(b * 32 + tt) * N_) + n) * 64 + ch];
        xs[bnL * TC5_XS + ch * 36 + 2 + tt] = pk2(v, v);
    }

    int bnL = tid / 128, t7 = tid % 128;
    int op = t7 & 31, t0 = (t7 >> 5) * 8;
    int ch0 = 2 * op, ch1 = 2 * op + 1;
    u64* xb = xs + bnL * TC5_XS;

    for (int p = 0; p < 3; p++) {
        __syncthreads();
        const float* W = Wt_all + p * 20480;
        for (int i = tid; i < 10240; i += TC5_THREADS) {
            int opx = i & 31, r = i >> 5;
            wsu[r * 32 + opx] = pk2(W[(2 * opx) * 320 + r], W[(2 * opx + 1) * 320 + r]);
        }
        __syncthreads();

        u64 bp = pk2(bt_all[p * 64 + ch0], bt_all[p * 64 + ch1]);
        u64 acc2[8];
        #pragma unroll
        for (int u = 0; u < 8; u++) acc2[u] = bp;

        for (int i = 0; i < 64; i++) {
            const u64* xi = xb + i * 36 + t0;
            u64 win[12];
            #pragma unroll
            for (int j = 0; j < 12; j++) win[j] = xi[j];
            const u64* wr = wsu + (i * 5) * 32 + op;
            u64 w0 = wr[0], w1 = wr[32], w2 = wr[64], w3 = wr[96], w4 = wr[128];
            #pragma unroll
            for (int u = 0; u < 8; u++) {
                u64 a = acc2[u];
                a = fma2(win[u],     w0, a);
                a = fma2(win[u + 1], w1, a);
                a = fma2(win[u + 2], w2, a);
                a = fma2(win[u + 3], w3, a);
                a = fma2(win[u + 4], w4, a);
                acc2[u] = a;
            }
        }
        __syncthreads();

        if (p < 2) {
            #pragma unroll
            for (int u = 0; u < 8; u++) {
                float a, b;
                upk2(acc2[u], a, b);
                int t = t0 + u;
                float x0, x1, dum;
                upk2(xb[ch0 * 36 + 2 + t], x0, dum);
                upk2(xb[ch1 * 36 + 2 + t], x1, dum);
                float n0 = gelu_f(a) + x0;
                float n1 = gelu_f(b) + x1;
                xb[ch0 * 36 + 2 + t] = pk2(n0, n0);
                xb[ch1 * 36 + 2 + t] = pk2(n1, n1);
            }
        } else {
            int bn = bn0 + bnL;
            float* ob = out + (size_t)bn * 2048;
            #pragma unroll
            for (int u = 0; u < 8; u++) {
                float a, b;
                upk2(acc2[u], a, b);
                int t = t0 + u;
                float x0, x1, dum;
                upk2(xb[ch0 * 36 + 2 + t], x0, dum);
                upk2(xb[ch1 * 36 + 2 + t], x1, dum);
                ob[ch0 * 32 + t] = gelu_f(a) + x0;
                ob[ch1 * 32 + t] = gelu_f(b) + x1;
            }
        }
    }
}

// ---------------- MLP1 split-K (scalar) ----------------
#define ZS_STRIDE 65
#define MLP1_SMEM ((G_ * ZS_STRIDE + 64 * 256) * 4)
__global__ void k_mlp1(const float* __restrict__ xt, const float* __restrict__ W1) {
    extern __shared__ __align__(16) float sm[];
    float* zs  = sm;
    float* w1s = sm + G_ * ZS_STRIDE;
    int n = blockIdx.x, tid = threadIdx.x;
    for (int i = tid; i < 8192; i += 256) {
        int b = i >> 11, c = (i >> 5) & 63, t = i & 31;
        zs[(b * 32 + t) * ZS_STRIDE + c] = xt[(((size_t)(b * N_ + n)) * 64 + c) * 32 + t];
    }
    for (int i = tid; i < 16384; i += 256)
        w1s[i] = W1[(size_t)n * 16384 + i];
    __syncthreads();
    int ow = tid & 31, gw = tid >> 5, o0 = ow * 8;
    float* pb = d_part + (size_t)n * (G_ * 256);
    for (int pass = 0; pass < 4; pass++) {
        int g0 = pass * 32 + gw * 4;
        float acc[4][8] = {};
        #pragma unroll 4
        for (int k = 0; k < 64; k++) {
            float4 wa = *(const float4*)&w1s[k * 256 + o0];
            float4 wb = *(const float4*)&w1s[k * 256 + o0 + 4];
            float wv[8] = {wa.x, wa.y, wa.z, wa.w, wb.x, wb.y, wb.z, wb.w};
            float z[4];
            #pragma unroll
            for (int j = 0; j < 4; j++) z[j] = zs[(g0 + j) * ZS_STRIDE + k];
            #pragma unroll
            for (int j = 0; j < 4; j++)
                #pragma unroll
                for (int q = 0; q < 8; q++)
                    acc[j][q] = fmaf(z[j], wv[q], acc[j][q]);
        }
        #pragma unroll
        for (int j = 0; j < 4; j++) {
            *(float4*)&pb[(g0 + j) * 256 + o0]     = make_float4(acc[j][0], acc[j][1], acc[j][2], acc[j][3]);
            *(float4*)&pb[(g0 + j) * 256 + o0 + 4] = make_float4(acc[j][4], acc[j][5], acc[j][6], acc[j][7]);
        }
    }
}

__global__ void k_redmlp2(const float* __restrict__ b1, const float* __restrict__ W2,
                          const float* __restrict__ b2, float* __restrict__ out) {
    __shared__ float hid[256];
    int g = blockIdx.x, o = threadIdx.x;
    float a0 = 0.f, a1 = 0.f;
    size_t base = (size_t)g * 256 + o;
    int nb = 0;
    for (; nb + 2 <= N_; nb += 2) {
        a0 += d_part[(size_t)nb * (G_ * 256) + base];
        a1 += d_part[(size_t)(nb + 1) * (G_ * 256) + base];
    }
    for (; nb < N_; nb++) a0 += d_part[(size_t)nb * (G_ * 256) + base];
    hid[o] = gelu_f(a0 + a1 + b1[o]);
    __syncthreads();
    if (o < 64) {
        float acc = b2[o];
        #pragma unroll 8
        for (int k = 0; k < 256; k++) acc = fmaf(hid[k], W2[k * 64 + o], acc);
        out[(size_t)g * 64 + o] = acc;
    }
}

extern "C" void kernel_launch(void* const* d_in, const int* in_sizes, int n_in,
                              void* d_out, int out_size) {
    float* out = (float*)d_out;
    static cudaStream_t s2 = nullptr;
    static cudaEvent_t evFork = nullptr, evX = nullptr, evJoin = nullptr;
    if (s2 == nullptr) {
        cudaStreamCreateWithFlags(&s2, cudaStreamNonBlocking);
        cudaEventCreateWithFlags(&evFork, cudaEventDisableTiming);
        cudaEventCreateWithFlags(&evX,    cudaEventDisableTiming);
        cudaEventCreateWithFlags(&evJoin, cudaEventDisableTiming);
        cudaFuncSetAttribute(k_gcn,    cudaFuncAttributeMaxDynamicSharedMemorySize, GCN_SMEM);
        cudaFuncSetAttribute(k_gat2,   cudaFuncAttributeMaxDynamicSharedMemorySize, GAT2_SMEM);
        cudaFuncSetAttribute(k_tconv3, cudaFuncAttributeMaxDynamicSharedMemorySize, TC5_SMEM);
        cudaFuncSetAttribute(k_mlp1,   cudaFuncAttributeMaxDynamicSharedMemorySize, MLP1_SMEM);
    }

    cudaEventRecord(evFork, 0);
    cudaStreamWaitEvent(s2, evFork, 0);
    cudaMemcpyToSymbolAsync(d_xin, d_in[0], (size_t)GN * H_ * 4, 0, cudaMemcpyDeviceToDevice, s2);
    cudaEventRecord(evX, s2);
    cudaMemcpyToSymbolAsync(d_W1c, d_in[13], (size_t)NH * 256 * 4, 0, cudaMemcpyDeviceToDevice, s2);
    k_stageB<<<48, 256, 0, s2>>>((const float*)d_in[9], (const float*)d_in[10],
                                 (const float*)d_in[14], (const float*)d_in[15],
                                 (const float*)d_in[16]);
    cudaEventRecord(evJoin, s2);

    k_stageA<<<64, 256>>>((const int*)d_in[1], (const float*)d_in[2],
                          (const float*)d_in[3], (const float*)d_in[4],
                          (const float*)d_in[5], (const float*)d_in[6],
                          (const float*)d_in[7], (const float*)d_in[8],
                          (const float*)d_in[11], (const float*)d_in[12]);
    k_prepA<<<1, CHUNK_>>>();
    k_prepB<<<(N_ + 3) / 4, 128>>>();
    k_prepC<<<(E2_ + 255) / 256, 256>>>();
    cudaStreamWaitEvent(0, evX, 0);

    float *xin, *Wg, *bg, *Wa, *asw, *adw, *ba, *Wt, *bt, *lng, *lnb, *W1, *b1, *W2, *b2;
    float *hbuf, *bufA, *xt0;
    cudaGetSymbolAddress((void**)&xin,  d_xin);
    cudaGetSymbolAddress((void**)&Wg,   d_Wg);
    cudaGetSymbolAddress((void**)&bg,   d_bg);
    cudaGetSymbolAddress((void**)&Wa,   d_Wa);
    cudaGetSymbolAddress((void**)&asw,  d_asw);
    cudaGetSymbolAddress((void**)&adw,  d_adw);
    cudaGetSymbolAddress((void**)&ba,   d_ba);
    cudaGetSymbolAddress((void**)&Wt,   d_Wt);
    cudaGetSymbolAddress((void**)&bt,   d_bt);
    cudaGetSymbolAddress((void**)&lng,  d_lngc);
    cudaGetSymbolAddress((void**)&lnb,  d_lnbc);
    cudaGetSymbolAddress((void**)&W1,   d_W1c);
    cudaGetSymbolAddress((void**)&b1,   d_b1c);
    cudaGetSymbolAddress((void**)&W2,   d_W2c);
    cudaGetSymbolAddress((void**)&b2,   d_b2c);
    cudaGetSymbolAddress((void**)&hbuf, d_h);
    cudaGetSymbolAddress((void**)&bufA, d_bufA);
    cudaGetSymbolAddress((void**)&xt0,  d_xt0);

    const float* hin = xin;
    for (int l = 0; l < 3; l++) {
        k_gcn<<<G_, LTH, GCN_SMEM>>>(hin, Wg + l * 4096, bg + l * 64, bufA);
        k_gat2<<<G_, LTH, GAT2_SMEM>>>(bufA, Wa + l * 4096, asw + l * 64, adw + l * 64,
                                       ba + l * 64, lng + l * 64, lnb + l * 64, hin, hbuf);
        hin = hbuf;
    }

    cudaStreamWaitEvent(0, evJoin, 0);
    k_tconv3<<<(B_ * N_) / TC5_BN, TC5_THREADS, TC5_SMEM>>>(hbuf, xt0, Wt, bt);

    k_mlp1<<<N_, 256, MLP1_SMEM>>>(xt0, W1);
    k_redmlp2<<<G_, 256>>>(b1, W2, b2, out);
}

// round 15
// speedup vs baseline: 1.1053x; 1.0109x over previous
#include <cuda_runtime.h>
#include <math.h>

#define B_   4
#define T_   32
#define N_   370
#define E_   11840
#define E2_  (E_ + N_)
#define G_   128
#define H_   64
#define GN   (G_ * N_)
#define NH   (N_ * H_)
#define CHUNK_ 512
#define DCAP 148
#define LTH  1024
#define NWARP (LTH / 32)
#define WSCR 740
#define GCH 368

typedef unsigned long long u64;
__device__ __forceinline__ u64 pk2(float lo, float hi) {
    u64 r; asm("mov.b64 %0,{%1,%2};" : "=l"(r) : "f"(lo), "f"(hi)); return r;
}
__device__ __forceinline__ void upk2(u64 v, float& lo, float& hi) {
    asm("mov.b64 {%0,%1},%2;" : "=f"(lo), "=f"(hi) : "l"(v));
}
__device__ __forceinline__ u64 fma2(u64 a, u64 b, u64 c) {
    u64 d; asm("fma.rn.f32x2 %0,%1,%2,%3;" : "=l"(d) : "l"(a), "l"(b), "l"(c)); return d;
}

__device__ float d_xin[GN * H_];
__device__ int   d_eic[2 * E_];
__device__ float d_ewc[E_];
__device__ float d_Wg[3 * 4096];
__device__ float d_bg[3 * 64];
__device__ float d_Wa[3 * 4096];
__device__ float d_asw[3 * 64];
__device__ float d_adw[3 * 64];
__device__ float d_ba[3 * 64];
__device__ float d_Wt[3 * 20480];
__device__ float d_bt[3 * 64];
__device__ float d_lngc[3 * 64];
__device__ float d_lnbc[3 * 64];
__device__ float d_W1c[NH * 256];
__device__ float d_b1c[256];
__device__ float d_W2c[256 * 64];
__device__ float d_b2c[64];

__device__ float  d_h[GN * H_];
__device__ float  d_bufA[GN * H_];
__device__ int    d_csr_ptr[N_ + 1];
__device__ int    d_csr_eid[E2_];
__device__ int    d_csr_dst[E2_];
__device__ float  d_dis[N_];
__device__ float2 d_csr_sg[E2_];      // {src*64 (bits), gnorm}
__device__ int    d_cnt[CHUNK_ * N_];
__device__ float  d_xt0[B_ * N_ * H_ * T_];
__device__ float  d_part[(size_t)G_ * N_ * 256];   // [g][n][256]

__device__ __forceinline__ float gelu_f(float x) {
    return 0.5f * x * (1.0f + erff(x * 0.70710678118654752f));
}

// ---------------- staging ----------------
__global__ void k_stageA(const int* ei, const float* ew, const float* Wg,
                         const float* bg, const float* Wa, const float* asw,
                         const float* adw, const float* ba, const float* lng,
                         const float* lnb) {
    int i0 = blockIdx.x * 256 + threadIdx.x, st = gridDim.x * 256;
    for (int i = i0; i < 2 * E_; i += st) d_eic[i] = ei[i];
    for (int i = i0; i < E_;    i += st) d_ewc[i] = ew[i];
    for (int i = i0; i < 12288; i += st) { d_Wg[i] = Wg[i]; d_Wa[i] = Wa[i]; }
    for (int i = i0; i < CHUNK_ * N_; i += st) d_cnt[i] = 0;
    for (int i = i0; i < 192;   i += st) {
        d_bg[i] = bg[i]; d_asw[i] = asw[i]; d_adw[i] = adw[i];
        d_ba[i] = ba[i]; d_lngc[i] = lng[i]; d_lnbc[i] = lnb[i];
    }
}
__global__ void k_stageB(const float* Wt, const float* bt, const float* b1,
                         const float* W2, const float* b2) {
    int i0 = blockIdx.x * 256 + threadIdx.x, st = gridDim.x * 256;
    for (int i = i0; i < 61440; i += st) d_Wt[i] = Wt[i];
    for (int i = i0; i < 192;   i += st) d_bt[i] = bt[i];
    for (int i = i0; i < 256;   i += st) d_b1c[i] = b1[i];
    for (int i = i0; i < 16384; i += st) d_W2c[i] = W2[i];
    for (int i = i0; i < 64;    i += st) d_b2c[i] = b2[i];
}

// ---------------- prep trio ----------------
__global__ void k_prepA() {
    int t = threadIdx.x;
    const int* dsts = d_eic + E_;
    const int EC = (E_ + CHUNK_ - 1) / CHUNK_;
    int e0 = t * EC, e1 = min(e0 + EC, E_);
    __shared__ int ptr_s[N_ + 1];
    for (int e = e0; e < e1; e++) d_cnt[t * N_ + dsts[e]]++;
    __syncthreads();
    if (t < N_) {
        int run = 0;
        for (int c = 0; c < CHUNK_; c++) {
            int idx = c * N_ + t;
            int v = d_cnt[idx]; d_cnt[idx] = run; run += v;
        }
        ptr_s[t] = run + 1;
    }
    __syncthreads();
    if (t == 0) {
        int p = 0;
        for (int n = 0; n < N_; n++) { int v = ptr_s[n]; ptr_s[n] = p; p += v; }
        ptr_s[N_] = p;
    }
    __syncthreads();
    if (t <= N_) d_csr_ptr[t] = ptr_s[t];
    for (int e = e0; e < e1; e++) {
        int d = dsts[e];
        int pos = ptr_s[d] + d_cnt[t * N_ + d]++;
        d_csr_eid[pos] = e; d_csr_dst[pos] = d;
    }
    __syncthreads();
    if (t < N_) {
        int pos = ptr_s[t + 1] - 1;
        d_csr_eid[pos] = E_ + t; d_csr_dst[pos] = t;
    }
}

__global__ void k_prepB() {
    int n = blockIdx.x * 4 + (threadIdx.x >> 5);
    int lane = threadIdx.x & 31;
    if (n >= N_) return;
    int p0 = d_csr_ptr[n], p1 = d_csr_ptr[n + 1] - 1;
    float s = 0.0f;
    for (int p = p0 + lane; p < p1; p += 32) s += d_ewc[d_csr_eid[p]];
    #pragma unroll
    for (int off = 16; off; off >>= 1) s += __shfl_xor_sync(~0u, s, off);
    if (lane == 0) d_dis[n] = rsqrtf(s + 1.0f);
}

__global__ void k_prepC() {
    int pos = blockIdx.x * 256 + threadIdx.x;
    if (pos >= E2_) return;
    int e = d_csr_eid[pos], d = d_csr_dst[pos];
    float dd = d_dis[d];
    int s; float gn;
    if (e < E_) { s = d_eic[e]; gn = d_dis[s] * d_ewc[e] * dd; }
    else        { s = d;        gn = dd * dd; }
    d_csr_sg[pos] = make_float2(__int_as_float(s * 64), gn);
}

// ------- in-block GEMM (1024 threads), two half-K passes, w[32] in regs -------
__device__ __forceinline__ void gemm_block(const float* __restrict__ in_s,
                                           const float* __restrict__ WsT,
                                           float* __restrict__ out_s, int tid) {
    int c = tid & 63, rb = tid >> 6;                 // rb in [0,16)
    const float* wc = WsT + c * 68;
    #pragma unroll
    for (int half = 0; half < 2; half++) {
        float w[32];
        #pragma unroll
        for (int k = 0; k < 32; k += 4)
            *(float4*)&w[k] = *(const float4*)&wc[half * 32 + k];
        const float* inh = in_s + half * 32;
        for (int r = rb; r < 185; r += 16) {
            int r2 = r + 185;
            float a0 = 0.f, a1 = 0.f, a2 = 0.f, a3 = 0.f;
            #pragma unroll
            for (int k = 0; k < 32; k += 4) {
                float4 h0 = *(const float4*)&inh[r * 64 + k];
                float4 h1 = *(const float4*)&inh[r2 * 64 + k];
                a0 = fmaf(h0.x, w[k], a0);     a1 = fmaf(h0.y, w[k + 1], a1);
                a0 = fmaf(h0.z, w[k + 2], a0); a1 = fmaf(h0.w, w[k + 3], a1);
                a2 = fmaf(h1.x, w[k], a2);     a3 = fmaf(h1.y, w[k + 1], a3);
                a2 = fmaf(h1.z, w[k + 2], a2); a3 = fmaf(h1.w, w[k + 3], a3);
            }
            float p01 = a0 + a1, p23 = a2 + a3;
            if (half == 0) {
                out_s[r * 64 + c]  = p01;
                out_s[r2 * 64 + c] = p23;
            } else {
                out_s[r * 64 + c]  += p01;
                out_s[r2 * 64 + c] += p23;
            }
        }
    }
}

// ---------------- K1: GCN layer (1024 threads) ----------------
#define GCN_SMEM ((2 * NH + 64 * 68) * 4)
__global__ void __launch_bounds__(LTH, 1)
k_gcn(const float* __restrict__ hin, const float* __restrict__ Wg,
      const float* __restrict__ bg, float* __restrict__ gout) {
    extern __shared__ __align__(16) float sm[];
    float* h_s  = sm;
    float* hw_s = sm + NH;
    float* WsT  = sm + 2 * NH;
    int g = blockIdx.x, tid = threadIdx.x;
    const float* hrow = hin + (size_t)g * NH;
    for (int i = tid * 4; i < NH; i += LTH * 4)
        *(float4*)&h_s[i] = *(const float4*)&hrow[i];
    for (int i = tid; i < 4096; i += LTH)
        WsT[(i & 63) * 68 + (i >> 6)] = Wg[i];
    __syncthreads();
    gemm_block(h_s, WsT, hw_s, tid);
    __syncthreads();

    int lane = tid & 31, w = tid >> 5;
    float2* scr = (float2*)(h_s + w * WSCR);
    float bx = bg[2 * lane], by = bg[2 * lane + 1];
    for (int d = w; d < N_; d += NWARP) {
        int p0 = d_csr_ptr[d], deg = d_csr_ptr[d + 1] - p0;
        float2 a0 = {0.f, 0.f}, a1 = {0.f, 0.f}, a2 = {0.f, 0.f}, a3 = {0.f, 0.f};
        for (int base = 0; base < deg; base += GCH) {
            int m = min(GCH, deg - base);
            for (int j = lane; j < m; j += 32) scr[j] = d_csr_sg[p0 + base + j];
            __syncwarp();
            int j = 0;
            for (; j + 4 <= m; j += 4) {
                float2 s0 = scr[j],     s1 = scr[j + 1];
                float2 s2 = scr[j + 2], s3 = scr[j + 3];
                float2 v0 = *(const float2*)&hw_s[__float_as_int(s0.x) + 2 * lane];
                float2 v1 = *(const float2*)&hw_s[__float_as_int(s1.x) + 2 * lane];
                float2 v2 = *(const float2*)&hw_s[__float_as_int(s2.x) + 2 * lane];
                float2 v3 = *(const float2*)&hw_s[__float_as_int(s3.x) + 2 * lane];
                a0.x = fmaf(s0.y, v0.x, a0.x); a0.y = fmaf(s0.y, v0.y, a0.y);
                a1.x = fmaf(s1.y, v1.x, a1.x); a1.y = fmaf(s1.y, v1.y, a1.y);
                a2.x = fmaf(s2.y, v2.x, a2.x); a2.y = fmaf(s2.y, v2.y, a2.y);
                a3.x = fmaf(s3.y, v3.x, a3.x); a3.y = fmaf(s3.y, v3.y, a3.y);
            }
            for (; j < m; j++) {
                float2 s0 = scr[j];
                float2 v0 = *(const float2*)&hw_s[__float_as_int(s0.x) + 2 * lane];
                a0.x = fmaf(s0.y, v0.x, a0.x); a0.y = fmaf(s0.y, v0.y, a0.y);
            }
            __syncwarp();
        }
        float gx = (a0.x + a1.x) + (a2.x + a3.x) + bx;
        float gy = (a0.y + a1.y) + (a2.y + a3.y) + by;
        *(float2*)&gout[((size_t)g * N_ + d) * 64 + 2 * lane] =
            make_float2(gelu_f(gx), gelu_f(gy));
    }
}

// ---------------- K2: GAT + residual + LN (1024 threads) ----------------
#define GAT2_SMEM ((2 * NH + 64 * 68 + N_ * 4) * 4)
__global__ void __launch_bounds__(LTH, 1)
k_gat2(const float* __restrict__ gin, const float* __restrict__ Wa,
       const float* __restrict__ attS, const float* __restrict__ attD,
       const float* __restrict__ ba, const float* __restrict__ lng,
       const float* __restrict__ lnb, const float* __restrict__ hin,
       float* __restrict__ hout) {
    extern __shared__ __align__(16) float sm[];
    float* g_s    = sm;
    float* gh_s   = sm + NH;
    float* WsT    = sm + 2 * NH;
    float* asrc_s = sm + 2 * NH + 64 * 68;
    int g = blockIdx.x, tid = threadIdx.x;
    const float* grow = gin + (size_t)g * NH;
    for (int i = tid * 4; i < NH; i += LTH * 4)
        *(float4*)&g_s[i] = *(const float4*)&grow[i];
    for (int i = tid; i < 4096; i += LTH)
        WsT[(i & 63) * 68 + (i >> 6)] = Wa[i];
    __syncthreads();
    gemm_block(g_s, WsT, gh_s, tid);
    __syncthreads();

    int lane = tid & 31, w = tid >> 5, hh = lane >> 3;
    float wsl = attS[lane], wsl2 = attS[lane + 32];
    float wdl = attD[lane], wdl2 = attD[lane + 32];
    for (int n = w; n < N_; n += NWARP) {
        float r1 = gh_s[n * 64 + lane] * wsl;
        float r2 = gh_s[n * 64 + 32 + lane] * wsl2;
        #pragma unroll
        for (int off = 8; off; off >>= 1) {
            r1 += __shfl_xor_sync(~0u, r1, off, 16);
            r2 += __shfl_xor_sync(~0u, r2, off, 16);
        }
        if (lane == 0)       { asrc_s[n * 4 + 0] = r1; asrc_s[n * 4 + 2] = r2; }
        else if (lane == 16) { asrc_s[n * 4 + 1] = r1; asrc_s[n * 4 + 3] = r2; }
    }
    __syncthreads();

    float* scrA = g_s + w * WSCR;
    int*   scrS = (int*)(scrA + DCAP * 4);
    float bx  = ba[2 * lane],  by  = ba[2 * lane + 1];
    float gsx = lng[2 * lane], gsy = lng[2 * lane + 1];
    float gbx = lnb[2 * lane], gby = lnb[2 * lane + 1];

    for (int d = w; d < N_; d += NWARP) {
        float r1 = gh_s[d * 64 + lane] * wdl;
        float r2 = gh_s[d * 64 + 32 + lane] * wdl2;
        #pragma unroll
        for (int off = 8; off; off >>= 1) {
            r1 += __shfl_xor_sync(~0u, r1, off, 16);
            r2 += __shfl_xor_sync(~0u, r2, off, 16);
        }
        float h0 = __shfl_sync(~0u, r1, 0),  h1 = __shfl_sync(~0u, r1, 16);
        float h2 = __shfl_sync(~0u, r2, 0),  h3 = __shfl_sync(~0u, r2, 16);

        int p0 = d_csr_ptr[d], deg = d_csr_ptr[d + 1] - p0;
        float2 acc = {0.f, 0.f};
        float invh;
        if (deg <= DCAP) {
            float m0 = -1e30f, m1 = -1e30f, m2 = -1e30f, m3 = -1e30f;
            for (int j = lane; j < deg; j += 32) {
                float2 sgv = d_csr_sg[p0 + j];
                int soff = __float_as_int(sgv.x);
                float4 av = *(const float4*)&asrc_s[soff >> 4];
                float a0 = av.x + h0, a1 = av.y + h1, a2 = av.z + h2, a3 = av.w + h3;
                a0 = fmaxf(a0, 0.2f * a0); a1 = fmaxf(a1, 0.2f * a1);
                a2 = fmaxf(a2, 0.2f * a2); a3 = fmaxf(a3, 0.2f * a3);
                scrA[j * 4 + 0] = a0; scrA[j * 4 + 1] = a1;
                scrA[j * 4 + 2] = a2; scrA[j * 4 + 3] = a3;
                scrS[j] = soff;
                m0 = fmaxf(m0, a0); m1 = fmaxf(m1, a1);
                m2 = fmaxf(m2, a2); m3 = fmaxf(m3, a3);
            }
            #pragma unroll
            for (int off = 16; off; off >>= 1) {
                m0 = fmaxf(m0, __shfl_xor_sync(~0u, m0, off));
                m1 = fmaxf(m1, __shfl_xor_sync(~0u, m1, off));
                m2 = fmaxf(m2, __shfl_xor_sync(~0u, m2, off));
                m3 = fmaxf(m3, __shfl_xor_sync(~0u, m3, off));
            }
            __syncwarp();
            float d0 = 0.f, d1 = 0.f, d2 = 0.f, d3 = 0.f;
            for (int j = lane; j < deg; j += 32) {
                float e0 = __expf(scrA[j * 4 + 0] - m0);
                float e1 = __expf(scrA[j * 4 + 1] - m1);
                float e2 = __expf(scrA[j * 4 + 2] - m2);
                float e3 = __expf(scrA[j * 4 + 3] - m3);
                scrA[j * 4 + 0] = e0; scrA[j * 4 + 1] = e1;
                scrA[j * 4 + 2] = e2; scrA[j * 4 + 3] = e3;
                d0 += e0; d1 += e1; d2 += e2; d3 += e3;
            }
            #pragma unroll
            for (int off = 16; off; off >>= 1) {
                d0 += __shfl_xor_sync(~0u, d0, off);
                d1 += __shfl_xor_sync(~0u, d1, off);
                d2 += __shfl_xor_sync(~0u, d2, off);
                d3 += __shfl_xor_sync(~0u, d3, off);
            }
            invh = 1.0f / ((hh == 0) ? d0 : (hh == 1) ? d1 : (hh == 2) ? d2 : d3);
            __syncwarp();
            float2 acc2 = {0.f, 0.f};
            int j = 0;
            for (; j + 2 <= deg; j += 2) {
                float al0 = scrA[j * 4 + hh], al1 = scrA[(j + 1) * 4 + hh];
                float2 v0 = *(const float2*)&gh_s[scrS[j] + 2 * lane];
                float2 v1 = *(const float2*)&gh_s[scrS[j + 1] + 2 * lane];
                acc.x  = fmaf(al0, v0.x, acc.x);  acc.y  = fmaf(al0, v0.y, acc.y);
                acc2.x = fmaf(al1, v1.x, acc2.x); acc2.y = fmaf(al1, v1.y, acc2.y);
            }
            if (j < deg) {
                float al = scrA[j * 4 + hh];
                float2 v = *(const float2*)&gh_s[scrS[j] + 2 * lane];
                acc.x = fmaf(al, v.x, acc.x); acc.y = fmaf(al, v.y, acc.y);
            }
            acc.x += acc2.x; acc.y += acc2.y;
        } else {
            float adh = (hh == 0) ? h0 : (hh == 1) ? h1 : (hh == 2) ? h2 : h3;
            float m = -1e30f;
            for (int p = p0; p < p0 + deg; p++) {
                float a = asrc_s[(__float_as_int(d_csr_sg[p].x) >> 4) + hh] + adh;
                a = fmaxf(a, 0.2f * a);
                m = fmaxf(m, a);
            }
            float den = 0.f;
            for (int p = p0; p < p0 + deg; p++) {
                int soff = __float_as_int(d_csr_sg[p].x);
                float a = asrc_s[(soff >> 4) + hh] + adh;
                a = fmaxf(a, 0.2f * a);
                float e = __expf(a - m);
                den += e;
                float2 v = *(const float2*)&gh_s[soff + 2 * lane];
                acc.x = fmaf(e, v.x, acc.x); acc.y = fmaf(e, v.y, acc.y);
            }
            invh = 1.0f / den;
        }
        float rx = acc.x * invh + bx + hin[((size_t)g * N_ + d) * 64 + 2 * lane];
        float ry = acc.y * invh + by + hin[((size_t)g * N_ + d) * 64 + 2 * lane + 1];
        float s1 = rx + ry, s2 = rx * rx + ry * ry;
        #pragma unroll
        for (int off = 16; off; off >>= 1) {
            s1 += __shfl_xor_sync(~0u, s1, off);
            s2 += __shfl_xor_sync(~0u, s2, off);
        }
        float mu = s1 * (1.0f / 64.0f);
        float var = fmaxf(s2 * (1.0f / 64.0f) - mu * mu, 0.0f);
        float inv = rsqrtf(var + 1e-5f);
        *(float2*)&hout[((size_t)g * N_ + d) * 64 + 2 * lane] =
            make_float2((rx - mu) * inv * gsx + gbx, (ry - mu) * inv * gsy + gby);
    }
}

// ------- fused 3-layer temporal conv, splatted f32x2, 5 bn x 640 threads -------
#define TC5_BN 5
#define TC5_THREADS 640
#define TC5_XS 2304
#define TC5_SMEM ((10240 + TC5_BN * TC5_XS) * 8)

__global__ void k_tconv3(const float* __restrict__ in_h, float* __restrict__ out,
                         const float* __restrict__ Wt_all, const float* __restrict__ bt_all) {
    extern __shared__ __align__(16) u64 smu[];
    u64* wsu = smu;
    u64* xs  = smu + 10240;
    int tid = threadIdx.x;
    int bn0 = blockIdx.x * TC5_BN;

    for (int i = tid; i < TC5_BN * TC5_XS; i += TC5_THREADS) xs[i] = 0ULL;
    __syncthreads();
    for (int idx = tid; idx < TC5_BN * 2048; idx += TC5_THREADS) {
        int bnL = idx >> 11, r = idx & 2047, bn = bn0 + bnL;
        int tt = r >> 6, ch = r & 63;
        int b = bn / N_, n = bn % N_;
        float v = in_h[(((size_t)(b * 32 + tt) * N_) + n) * 64 + ch];
        xs[bnL * TC5_XS + ch * 36 + 2 + tt] = pk2(v, v);
    }

    int bnL = tid / 128, t7 = tid % 128;
    int op = t7 & 31, t0 = (t7 >> 5) * 8;
    int ch0 = 2 * op, ch1 = 2 * op + 1;
    u64* xb = xs + bnL * TC5_XS;

    for (int p = 0; p < 3; p++) {
        __syncthreads();
        const float* W = Wt_all + p * 20480;
        for (int i = tid; i < 10240; i += TC5_THREADS) {
            int opx = i & 31, r = i >> 5;
            wsu[r * 32 + opx] = pk2(W[(2 * opx) * 320 + r], W[(2 * opx + 1) * 320 + r]);
        }
        __syncthreads();

        u64 bp = pk2(bt_all[p * 64 + ch0], bt_all[p * 64 + ch1]);
        u64 acc2[8];
        #pragma unroll
        for (int u = 0; u < 8; u++) acc2[u] = bp;

        for (int i = 0; i < 64; i++) {
            const u64* xi = xb + i * 36 + t0;
            u64 win[12];
            #pragma unroll
            for (int j = 0; j < 12; j++) win[j] = xi[j];
            const u64* wr = wsu + (i * 5) * 32 + op;
            u64 w0 = wr[0], w1 = wr[32], w2 = wr[64], w3 = wr[96], w4 = wr[128];
            #pragma unroll
            for (int u = 0; u < 8; u++) {
                u64 a = acc2[u];
                a = fma2(win[u],     w0, a);
                a = fma2(win[u + 1], w1, a);
                a = fma2(win[u + 2], w2, a);
                a = fma2(win[u + 3], w3, a);
                a = fma2(win[u + 4], w4, a);
                acc2[u] = a;
            }
        }
        __syncthreads();

        if (p < 2) {
            #pragma unroll
            for (int u = 0; u < 8; u++) {
                float a, b;
                upk2(acc2[u], a, b);
                int t = t0 + u;
                float x0, x1, dum;
                upk2(xb[ch0 * 36 + 2 + t], x0, dum);
                upk2(xb[ch1 * 36 + 2 + t], x1, dum);
                float n0 = gelu_f(a) + x0;
                float n1 = gelu_f(b) + x1;
                xb[ch0 * 36 + 2 + t] = pk2(n0, n0);
                xb[ch1 * 36 + 2 + t] = pk2(n1, n1);
            }
        } else {
            int bn = bn0 + bnL;
            float* ob = out + (size_t)bn * 2048;
            #pragma unroll
            for (int u = 0; u < 8; u++) {
                float a, b;
                upk2(acc2[u], a, b);
                int t = t0 + u;
                float x0, x1, dum;
                upk2(xb[ch0 * 36 + 2 + t], x0, dum);
                upk2(xb[ch1 * 36 + 2 + t], x1, dum);
                ob[ch0 * 32 + t] = gelu_f(a) + x0;
                ob[ch1 * 32 + t] = gelu_f(b) + x1;
            }
        }
    }
}

// ---------------- MLP1 split-K, d_part[g][n][256] ----------------
#define ZS_STRIDE 65
#define MLP1_SMEM ((G_ * ZS_STRIDE + 64 * 256) * 4)
__global__ void k_mlp1(const float* __restrict__ xt, const float* __restrict__ W1) {
    extern __shared__ __align__(16) float sm[];
    float* zs  = sm;
    float* w1s = sm + G_ * ZS_STRIDE;
    int n = blockIdx.x, tid = threadIdx.x;
    for (int i = tid; i < 8192; i += 256) {
        int b = i >> 11, c = (i >> 5) & 63, t = i & 31;
        zs[(b * 32 + t) * ZS_STRIDE + c] = xt[(((size_t)(b * N_ + n)) * 64 + c) * 32 + t];
    }
    for (int i = tid; i < 16384; i += 256)
        w1s[i] = W1[(size_t)n * 16384 + i];
    __syncthreads();
    int ow = tid & 31, gw = tid >> 5, o0 = ow * 8;
    for (int pass = 0; pass < 4; pass++) {
        int g0 = pass * 32 + gw * 4;
        float acc[4][8] = {};
        #pragma unroll 4
        for (int k = 0; k < 64; k++) {
            float4 wa = *(const float4*)&w1s[k * 256 + o0];
            float4 wb = *(const float4*)&w1s[k * 256 + o0 + 4];
            float wv[8] = {wa.x, wa.y, wa.z, wa.w, wb.x, wb.y, wb.z, wb.w};
            float z[4];
            #pragma unroll
            for (int j = 0; j < 4; j++) z[j] = zs[(g0 + j) * ZS_STRIDE + k];
            #pragma unroll
            for (int j = 0; j < 4; j++)
                #pragma unroll
                for (int q = 0; q < 8; q++)
                    acc[j][q] = fmaf(z[j], wv[q], acc[j][q]);
        }
        #pragma unroll
        for (int j = 0; j < 4; j++) {
            size_t base = ((size_t)(g0 + j) * N_ + n) * 256;
            *(float4*)&d_part[base + o0]     = make_float4(acc[j][0], acc[j][1], acc[j][2], acc[j][3]);
            *(float4*)&d_part[base + o0 + 4] = make_float4(acc[j][4], acc[j][5], acc[j][6], acc[j][7]);
        }
    }
}

__global__ void k_redmlp2(const float* __restrict__ b1, const float* __restrict__ W2,
                          const float* __restrict__ b2, float* __restrict__ out) {
    __shared__ float hid[256];
    int g = blockIdx.x, o = threadIdx.x;
    const float* pg = d_part + (size_t)g * N_ * 256 + o;
    float a0 = 0.f, a1 = 0.f, a2 = 0.f, a3 = 0.f;
    int nb = 0;
    for (; nb + 4 <= N_; nb += 4) {
        a0 += pg[(size_t)nb * 256];
        a1 += pg[(size_t)(nb + 1) * 256];
        a2 += pg[(size_t)(nb + 2) * 256];
        a3 += pg[(size_t)(nb + 3) * 256];
    }
    for (; nb < N_; nb++) a0 += pg[(size_t)nb * 256];
    hid[o] = gelu_f((a0 + a1) + (a2 + a3) + b1[o]);
    __syncthreads();
    if (o < 64) {
        float acc = b2[o];
        #pragma unroll 8
        for (int k = 0; k < 256; k++) acc = fmaf(hid[k], W2[k * 64 + o], acc);
        out[(size_t)g * 64 + o] = acc;
    }
}

extern "C" void kernel_launch(void* const* d_in, const int* in_sizes, int n_in,
                              void* d_out, int out_size) {
    float* out = (float*)d_out;
    static cudaStream_t s2 = nullptr;
    static cudaEvent_t evFork = nullptr, evX = nullptr, evJoin = nullptr;
    if (s2 == nullptr) {
        cudaStreamCreateWithFlags(&s2, cudaStreamNonBlocking);
        cudaEventCreateWithFlags(&evFork, cudaEventDisableTiming);
        cudaEventCreateWithFlags(&evX,    cudaEventDisableTiming);
        cudaEventCreateWithFlags(&evJoin, cudaEventDisableTiming);
        cudaFuncSetAttribute(k_gcn,    cudaFuncAttributeMaxDynamicSharedMemorySize, GCN_SMEM);
        cudaFuncSetAttribute(k_gat2,   cudaFuncAttributeMaxDynamicSharedMemorySize, GAT2_SMEM);
        cudaFuncSetAttribute(k_tconv3, cudaFuncAttributeMaxDynamicSharedMemorySize, TC5_SMEM);
        cudaFuncSetAttribute(k_mlp1,   cudaFuncAttributeMaxDynamicSharedMemorySize, MLP1_SMEM);
    }

    cudaEventRecord(evFork, 0);
    cudaStreamWaitEvent(s2, evFork, 0);
    cudaMemcpyToSymbolAsync(d_xin, d_in[0], (size_t)GN * H_ * 4, 0, cudaMemcpyDeviceToDevice, s2);
    cudaEventRecord(evX, s2);
    cudaMemcpyToSymbolAsync(d_W1c, d_in[13], (size_t)NH * 256 * 4, 0, cudaMemcpyDeviceToDevice, s2);
    k_stageB<<<48, 256, 0, s2>>>((const float*)d_in[9], (const float*)d_in[10],
                                 (const float*)d_in[14], (const float*)d_in[15],
                                 (const float*)d_in[16]);
    cudaEventRecord(evJoin, s2);

    k_stageA<<<64, 256>>>((const int*)d_in[1], (const float*)d_in[2],
                          (const float*)d_in[3], (const float*)d_in[4],
                          (const float*)d_in[5], (const float*)d_in[6],
                          (const float*)d_in[7], (const float*)d_in[8],
                          (const float*)d_in[11], (const float*)d_in[12]);
    k_prepA<<<1, CHUNK_>>>();
    k_prepB<<<(N_ + 3) / 4, 128>>>();
    k_prepC<<<(E2_ + 255) / 256, 256>>>();
    cudaStreamWaitEvent(0, evX, 0);

    float *xin, *Wg, *bg, *Wa, *asw, *adw, *ba, *Wt, *bt, *lng, *lnb, *W1, *b1, *W2, *b2;
    float *hbuf, *bufA, *xt0;
    cudaGetSymbolAddress((void**)&xin,  d_xin);
    cudaGetSymbolAddress((void**)&Wg,   d_Wg);
    cudaGetSymbolAddress((void**)&bg,   d_bg);
    cudaGetSymbolAddress((void**)&Wa,   d_Wa);
    cudaGetSymbolAddress((void**)&asw,  d_asw);
    cudaGetSymbolAddress((void**)&adw,  d_adw);
    cudaGetSymbolAddress((void**)&ba,   d_ba);
    cudaGetSymbolAddress((void**)&Wt,   d_Wt);
    cudaGetSymbolAddress((void**)&bt,   d_bt);
    cudaGetSymbolAddress((void**)&lng,  d_lngc);
    cudaGetSymbolAddress((void**)&lnb,  d_lnbc);
    cudaGetSymbolAddress((void**)&W1,   d_W1c);
    cudaGetSymbolAddress((void**)&b1,   d_b1c);
    cudaGetSymbolAddress((void**)&W2,   d_W2c);
    cudaGetSymbolAddress((void**)&b2,   d_b2c);
    cudaGetSymbolAddress((void**)&hbuf, d_h);
    cudaGetSymbolAddress((void**)&bufA, d_bufA);
    cudaGetSymbolAddress((void**)&xt0,  d_xt0);

    const float* hin = xin;
    for (int l = 0; l < 3; l++) {
        k_gcn<<<G_, LTH, GCN_SMEM>>>(hin, Wg + l * 4096, bg + l * 64, bufA);
        k_gat2<<<G_, LTH, GAT2_SMEM>>>(bufA, Wa + l * 4096, asw + l * 64, adw + l * 64,
                                       ba + l * 64, lng + l * 64, lnb + l * 64, hin, hbuf);
        hin = hbuf;
    }

    cudaStreamWaitEvent(0, evJoin, 0);
    k_tconv3<<<(B_ * N_) / TC5_BN, TC5_THREADS, TC5_SMEM>>>(hbuf, xt0, Wt, bt);

    k_mlp1<<<N_, 256, MLP1_SMEM>>>(xt0, W1);
    k_redmlp2<<<G_, 256>>>(b1, W2, b2, out);
}